// round 6
// baseline (speedup 1.0000x reference)
#include <cuda_runtime.h>
#include <cuda_bf16.h>
#include <math_constants.h>

#define BATCH 4
#define SEQ   2048
#define CH    256
#define HEADS 8
#define DH    32
#define BH    (BATCH*HEADS)
#define M_ROWS (BATCH*SEQ)

typedef unsigned long long u64;

__device__ float g_q[BH * SEQ * DH];
__device__ float g_k[BH * SEQ * DH];
__device__ float g_v[BH * SEQ * DH];
__device__ float g_att[BATCH * SEQ * CH];

// ---------------------------------------------------------------------------
// Packed f32x2 helpers (Blackwell sm_100+: FFMA2 path, 2x fp32 throughput)
// ---------------------------------------------------------------------------
__device__ __forceinline__ u64 pk2(float lo, float hi) {
    u64 r; asm("mov.b64 %0,{%1,%2};" : "=l"(r) : "f"(lo), "f"(hi)); return r;
}
__device__ __forceinline__ void upk2(u64 v, float& lo, float& hi) {
    asm("mov.b64 {%0,%1},%2;" : "=f"(lo), "=f"(hi) : "l"(v));
}
__device__ __forceinline__ void ffma2(u64& d, u64 a, u64 b) {
    asm("fma.rn.f32x2 %0,%1,%2,%0;" : "+l"(d) : "l"(a), "l"(b));
}
__device__ __forceinline__ u64 fadd2(u64 a, u64 b) {
    u64 r; asm("add.rn.f32x2 %0,%1,%2;" : "=l"(r) : "l"(a), "l"(b)); return r;
}
__device__ __forceinline__ u64 fmul2(u64 a, u64 b) {
    u64 r; asm("mul.rn.f32x2 %0,%1,%2;" : "=l"(r) : "l"(a), "l"(b)); return r;
}

// Mask: lengths in [1,2048]; int64 vs int32 sniff (word[1]==0 => int64).
__device__ __forceinline__ int read_len(const void* kpm, int b)
{
    const int* p32 = (const int*)kpm;
    int len = (p32[1] == 0) ? (int)((const long long*)kpm)[b] : p32[b];
    if (len < 1)   len = 1;
    if (len > SEQ) len = SEQ;
    return len;
}

// ---------------------------------------------------------------------------
// Epilogue functors
// ---------------------------------------------------------------------------
struct QkvEpilogue {
    __device__ __forceinline__ void operator()(
        int bm_, int bn_, const int* roff, const int* coff,
        float (&acc)[8][8]) const
    {
#pragma unroll
        for (int i = 0; i < 8; i++) {
            const int m  = bm_ + roff[i];
            const int b  = m >> 11;
            const int nq = m & 2047;
#pragma unroll
            for (int j = 0; j < 8; j++) {
                const int n = bn_ + coff[j];
                const int s = n >> 8;        // 0=q 1=k 2=v
                const int h = (n >> 5) & 7;
                const int d = n & 31;
                float* dst = (s == 0) ? g_q : ((s == 1) ? g_k : g_v);
                dst[(((size_t)(b * 8 + h)) * SEQ + nq) * DH + d] = acc[i][j];
            }
        }
    }
};

struct ProjEpilogue {
    float* out;
    const float* bias;
    __device__ __forceinline__ void operator()(
        int bm_, int bn_, const int* roff, const int* coff,
        float (&acc)[8][8]) const
    {
#pragma unroll
        for (int i = 0; i < 8; i++) {
            const int m = bm_ + roff[i];
#pragma unroll
            for (int j = 0; j < 8; j++) {
                const int n = bn_ + coff[j];
                out[(size_t)m * 256 + n] = acc[i][j] + bias[n];
            }
        }
    }
};

// ---------------------------------------------------------------------------
// 128x128x8 double-buffered NT GEMM, FFMA2 inner loop.
// 256 threads, 8x8 per thread (paired along n into 8x4 f32x2 accumulators).
// ---------------------------------------------------------------------------
template <typename Epilogue>
__device__ __forceinline__ void gemm128x128(
    const float* __restrict__ A, const float* __restrict__ B,
    int bm, int bn, const Epilogue& epi)
{
    __shared__ __align__(16) float As[2][8][132];
    __shared__ __align__(16) float Bs[2][8][132];

    const int tid = threadIdx.x;
    const int lr = tid >> 1;          // 0..127
    const int lc = (tid & 1) * 4;     // 0 or 4
    const int tr0 = (tid >> 4) * 4;   // 0..60
    const int tc0 = (tid & 15) * 4;   // 0..60

    u64 acc2[8][4];
#pragma unroll
    for (int i = 0; i < 8; i++)
#pragma unroll
        for (int j = 0; j < 4; j++) acc2[i][j] = 0ull;

    // prologue: tile 0
    float4 av = *(const float4*)&A[(size_t)(bm + lr) * 256 + lc];
    float4 bv = *(const float4*)&B[(size_t)(bn + lr) * 256 + lc];
    As[0][lc + 0][lr] = av.x; As[0][lc + 1][lr] = av.y;
    As[0][lc + 2][lr] = av.z; As[0][lc + 3][lr] = av.w;
    Bs[0][lc + 0][lr] = bv.x; Bs[0][lc + 1][lr] = bv.y;
    Bs[0][lc + 2][lr] = bv.z; Bs[0][lc + 3][lr] = bv.w;
    __syncthreads();

    int buf = 0;
    for (int k0 = 0; k0 < 256; k0 += 8) {
        const int nxt = k0 + 8;
        float4 an, bn4;
        if (nxt < 256) {
            an  = *(const float4*)&A[(size_t)(bm + lr) * 256 + nxt + lc];
            bn4 = *(const float4*)&B[(size_t)(bn + lr) * 256 + nxt + lc];
        }
#pragma unroll
        for (int kk = 0; kk < 8; kk++) {
            float4 a0 = *(const float4*)&As[buf][kk][tr0];
            float4 a1 = *(const float4*)&As[buf][kk][tr0 + 64];
            ulonglong2 bA = *(const ulonglong2*)&Bs[buf][kk][tc0];
            ulonglong2 bB = *(const ulonglong2*)&Bs[buf][kk][tc0 + 64];
            u64 b2[4] = {bA.x, bA.y, bB.x, bB.y};
            float ar[8] = {a0.x, a0.y, a0.z, a0.w, a1.x, a1.y, a1.z, a1.w};
            u64 as2[8];
#pragma unroll
            for (int i = 0; i < 8; i++) as2[i] = pk2(ar[i], ar[i]);
#pragma unroll
            for (int i = 0; i < 8; i++)
#pragma unroll
                for (int j = 0; j < 4; j++) ffma2(acc2[i][j], as2[i], b2[j]);
        }
        if (nxt < 256) {
            const int nb = buf ^ 1;
            As[nb][lc + 0][lr] = an.x;  As[nb][lc + 1][lr] = an.y;
            As[nb][lc + 2][lr] = an.z;  As[nb][lc + 3][lr] = an.w;
            Bs[nb][lc + 0][lr] = bn4.x; Bs[nb][lc + 1][lr] = bn4.y;
            Bs[nb][lc + 2][lr] = bn4.z; Bs[nb][lc + 3][lr] = bn4.w;
            buf = nb;
            __syncthreads();
        }
    }

    // unpack + epilogue
    float acc[8][8];
#pragma unroll
    for (int i = 0; i < 8; i++)
#pragma unroll
        for (int j = 0; j < 4; j++) upk2(acc2[i][j], acc[i][2*j], acc[i][2*j + 1]);

    int roff[8], coff[8];
#pragma unroll
    for (int i = 0; i < 4; i++) {
        roff[i] = tr0 + i;      roff[i + 4] = tr0 + 64 + i;
        coff[i] = tc0 + i;      coff[i + 4] = tc0 + 64 + i;
    }
    epi(bm, bn, roff, coff, acc);
}

__global__ __launch_bounds__(256) void qkv_gemm_kernel(
    const float* __restrict__ X, const float* __restrict__ W)
{
    QkvEpilogue epi;
    gemm128x128(X, W, blockIdx.x * 128, blockIdx.y * 128, epi);
}

__global__ __launch_bounds__(256) void proj_gemm_kernel(
    const float* __restrict__ Wp, const float* __restrict__ bias,
    float* __restrict__ out)
{
    ProjEpilogue epi{out, bias};
    gemm128x128(g_att, Wp, blockIdx.x * 128, blockIdx.y * 128, epi);
}

// ---------------------------------------------------------------------------
// Flash attention: 128 threads, 2 query rows per thread (rows t and t+128),
// FFMA2 math, 8-key register chunks, branch-free masked softmax.
// ---------------------------------------------------------------------------
__global__ __launch_bounds__(128) void attn_kernel(const void* __restrict__ kpm)
{
    const int bh = blockIdx.y;
    const int b  = bh >> 3;
    const int h  = bh & 7;
    const int r0 = blockIdx.x * 256 + threadIdx.x;   // second row: r0 + 128

    const int len = read_len(kpm, b);
    const float scale = 0.17677669529663687f;   // 1/sqrt(32)

    u64 q2[2][16];
#pragma unroll
    for (int qi = 0; qi < 2; qi++) {
        const ulonglong2* qp = (const ulonglong2*)(g_q + ((size_t)bh * SEQ + r0 + qi * 128) * DH);
#pragma unroll
        for (int i = 0; i < 8; i++) {
            ulonglong2 t = qp[i];
            q2[qi][2*i] = t.x; q2[qi][2*i + 1] = t.y;
        }
    }

    u64 o2[2][16];
#pragma unroll
    for (int qi = 0; qi < 2; qi++)
#pragma unroll
        for (int i = 0; i < 16; i++) o2[qi][i] = 0ull;   // bits of (+0.f,+0.f)

    float m0 = -CUDART_INF_F, m1 = -CUDART_INF_F;
    float l0 = 0.f, l1 = 0.f;

    __shared__ __align__(16) float ks[64][DH];
    __shared__ __align__(16) float vs[64][DH];

    const int ntiles = (len + 63) >> 6;
    for (int kt = 0; kt < ntiles; kt++) {
        __syncthreads();
        {
            const float4* kb = (const float4*)(g_k + ((size_t)bh * SEQ + kt * 64) * DH);
            const float4* vb = (const float4*)(g_v + ((size_t)bh * SEQ + kt * 64) * DH);
            float4* kd = (float4*)ks;
            float4* vd = (float4*)vs;
#pragma unroll
            for (int i = 0; i < 4; i++) {
                const int idx = threadIdx.x + i * 128;
                kd[idx] = kb[idx];
                vd[idx] = vb[idx];
            }
        }
        __syncthreads();

        const int jmax = min(64, len - kt * 64);
#pragma unroll 1
        for (int c = 0; c < 64; c += 8) {
            if (c >= jmax) break;
            float s[2][8];
#pragma unroll
            for (int jj = 0; jj < 8; jj++) {
                const ulonglong2* kj = (const ulonglong2*)ks[c + jj];
                u64 a00 = 0ull, a01 = 0ull, a10 = 0ull, a11 = 0ull;
#pragma unroll
                for (int i = 0; i < 8; i++) {
                    ulonglong2 kk = kj[i];
                    ffma2(a00, q2[0][2*i],     kk.x);
                    ffma2(a01, q2[0][2*i + 1], kk.y);
                    ffma2(a10, q2[1][2*i],     kk.x);
                    ffma2(a11, q2[1][2*i + 1], kk.y);
                }
                u64 t0 = fadd2(a00, a01);
                u64 t1 = fadd2(a10, a11);
                float lo, hi;
                upk2(t0, lo, hi); float sv0 = (lo + hi) * scale;
                upk2(t1, lo, hi); float sv1 = (lo + hi) * scale;
                const bool valid = (c + jj) < jmax;
                s[0][jj] = valid ? sv0 : -CUDART_INF_F;
                s[1][jj] = valid ? sv1 : -CUDART_INF_F;
            }

            // chunk max + uniform rescale (branch-free)
            float c0 = s[0][0], c1 = s[1][0];
#pragma unroll
            for (int jj = 1; jj < 8; jj++) { c0 = fmaxf(c0, s[0][jj]); c1 = fmaxf(c1, s[1][jj]); }
            const float n0 = fmaxf(m0, c0), n1 = fmaxf(m1, c1);
            const float cr0 = __expf(m0 - n0), cr1 = __expf(m1 - n1);  // exp(-inf)=0 first time
            l0 *= cr0; l1 *= cr1;
            const u64 cr02 = pk2(cr0, cr0), cr12 = pk2(cr1, cr1);
#pragma unroll
            for (int i = 0; i < 16; i++) {
                o2[0][i] = fmul2(o2[0][i], cr02);
                o2[1][i] = fmul2(o2[1][i], cr12);
            }
            m0 = n0; m1 = n1;

#pragma unroll
            for (int jj = 0; jj < 8; jj++) {
                const float p0 = __expf(s[0][jj] - m0);
                const float p1 = __expf(s[1][jj] - m1);
                l0 += p0; l1 += p1;
                const u64 p02 = pk2(p0, p0), p12 = pk2(p1, p1);
                const ulonglong2* vj = (const ulonglong2*)vs[c + jj];
#pragma unroll
                for (int i = 0; i < 8; i++) {
                    ulonglong2 vv = vj[i];
                    ffma2(o2[0][2*i],     p02, vv.x);
                    ffma2(o2[0][2*i + 1], p02, vv.y);
                    ffma2(o2[1][2*i],     p12, vv.x);
                    ffma2(o2[1][2*i + 1], p12, vv.y);
                }
            }
        }
    }

    // normalize + store both rows
#pragma unroll
    for (int qi = 0; qi < 2; qi++) {
        const float inv = 1.f / (qi == 0 ? l0 : l1);
        const int row = r0 + qi * 128;
        float4* op = (float4*)(g_att + ((size_t)(b * SEQ + row)) * CH + h * DH);
#pragma unroll
        for (int i = 0; i < 8; i++) {
            float e0, e1, e2, e3;
            upk2(o2[qi][2*i],     e0, e1);
            upk2(o2[qi][2*i + 1], e2, e3);
            float4 t;
            t.x = e0 * inv; t.y = e1 * inv; t.z = e2 * inv; t.w = e3 * inv;
            op[i] = t;
        }
    }
}

// ---------------------------------------------------------------------------
// Launch: resolve inputs by element count.
// ---------------------------------------------------------------------------
extern "C" void kernel_launch(void* const* d_in, const int* in_sizes, int n_in,
                              void* d_out, int out_size)
{
    (void)out_size;
    const float* x = nullptr; const void* kpm = nullptr;
    const float* w_qkv = nullptr; const float* w_proj = nullptr;
    const float* b_proj = nullptr;

    for (int i = 0; i < n_in; i++) {
        switch (in_sizes[i]) {
            case 2097152: x      = (const float*)d_in[i]; break;
            case 4:       kpm    = d_in[i];               break;
            case 196608:  w_qkv  = (const float*)d_in[i]; break;
            case 65536:   w_proj = (const float*)d_in[i]; break;
            case 256:     b_proj = (const float*)d_in[i]; break;
            default: break;
        }
    }
    float* out = (float*)d_out;

    {   // QKV: 8192 x 768
        dim3 grid(M_ROWS / 128, 768 / 128);
        qkv_gemm_kernel<<<grid, 256>>>(x, w_qkv);
    }
    {   // attention: 256 rows per block (2 per thread)
        dim3 grid(SEQ / 256, BH);
        attn_kernel<<<grid, 128>>>(kpm);
    }
    {   // proj: 8192 x 256
        dim3 grid(M_ROWS / 128, 256 / 128);
        proj_gemm_kernel<<<grid, 256>>>(w_proj, b_proj, out);
    }
}

// round 8
// speedup vs baseline: 1.9122x; 1.9122x over previous
#include <cuda_runtime.h>
#include <cuda_bf16.h>
#include <math_constants.h>

#define BATCH 4
#define SEQ   2048
#define CH    256
#define HEADS 8
#define DH    32
#define BH    (BATCH*HEADS)
#define M_ROWS (BATCH*SEQ)

typedef unsigned long long u64;
typedef unsigned int u32;

// ---------------------------------------------------------------------------
// Scratch: split-precision bf16 Q/K (row-major) and V (transposed), fp32 att.
// ---------------------------------------------------------------------------
__device__ __nv_bfloat16 g_qh[BH * SEQ * DH];
__device__ __nv_bfloat16 g_ql[BH * SEQ * DH];
__device__ __nv_bfloat16 g_kh[BH * SEQ * DH];
__device__ __nv_bfloat16 g_kl[BH * SEQ * DH];
__device__ __nv_bfloat16 g_vh[BH * DH * SEQ];   // [bh][dh][seq]
__device__ __nv_bfloat16 g_vl[BH * DH * SEQ];
__device__ float g_att[BATCH * SEQ * CH];

// ---------------------------------------------------------------------------
// Packed f32x2 helpers (kept for GEMM: saves issue slots)
// ---------------------------------------------------------------------------
__device__ __forceinline__ u64 pk2(float lo, float hi) {
    u64 r; asm("mov.b64 %0,{%1,%2};" : "=l"(r) : "f"(lo), "f"(hi)); return r;
}
__device__ __forceinline__ void upk2(u64 v, float& lo, float& hi) {
    asm("mov.b64 {%0,%1},%2;" : "=f"(lo), "=f"(hi) : "l"(v));
}
__device__ __forceinline__ void ffma2(u64& d, u64 a, u64 b) {
    asm("fma.rn.f32x2 %0,%1,%2,%0;" : "+l"(d) : "l"(a), "l"(b));
}

// ---------------------------------------------------------------------------
// mma.sync wrappers (bf16 -> fp32 accum)
// ---------------------------------------------------------------------------
__device__ __forceinline__ void mma16816(float* d, const u32* a, u32 b0, u32 b1) {
    asm volatile(
        "mma.sync.aligned.m16n8k16.row.col.f32.bf16.bf16.f32 "
        "{%0,%1,%2,%3},{%4,%5,%6,%7},{%8,%9},{%0,%1,%2,%3};"
        : "+f"(d[0]), "+f"(d[1]), "+f"(d[2]), "+f"(d[3])
        : "r"(a[0]), "r"(a[1]), "r"(a[2]), "r"(a[3]), "r"(b0), "r"(b1));
}
__device__ __forceinline__ void mma16808(float* d, u32 a0, u32 a1, u32 b0) {
    asm volatile(
        "mma.sync.aligned.m16n8k8.row.col.f32.bf16.bf16.f32 "
        "{%0,%1,%2,%3},{%4,%5},{%6},{%0,%1,%2,%3};"
        : "+f"(d[0]), "+f"(d[1]), "+f"(d[2]), "+f"(d[3])
        : "r"(a0), "r"(a1), "r"(b0));
}
__device__ __forceinline__ u32 pack_bf(__nv_bfloat16 a, __nv_bfloat16 b) {
    return ((u32)__bfloat16_as_ushort(b) << 16) | (u32)__bfloat16_as_ushort(a);
}

// Mask: lengths in [1,2048]; int64 vs int32 sniff (word[1]==0 => int64).
__device__ __forceinline__ int read_len(const void* kpm, int b)
{
    const int* p32 = (const int*)kpm;
    int len = (p32[1] == 0) ? (int)((const long long*)kpm)[b] : p32[b];
    if (len < 1)   len = 1;
    if (len > SEQ) len = SEQ;
    return len;
}

// ---------------------------------------------------------------------------
// Epilogues
// ---------------------------------------------------------------------------
struct QkvEpilogue {
    __device__ __forceinline__ void operator()(
        int bm_, int bn_, const int* roff, const int* coff,
        float (&acc)[8][8]) const
    {
#pragma unroll
        for (int i = 0; i < 8; i++) {
            const int m  = bm_ + roff[i];
            const int b  = m >> 11;
            const int nq = m & 2047;
#pragma unroll
            for (int j = 0; j < 8; j++) {
                const int n = bn_ + coff[j];
                const int s = n >> 8;        // 0=q 1=k 2=v
                const int h = (n >> 5) & 7;
                const int d = n & 31;
                const float val = acc[i][j];
                const __nv_bfloat16 hi = __float2bfloat16(val);
                const __nv_bfloat16 lo = __float2bfloat16(val - __bfloat162float(hi));
                const size_t bh = (size_t)(b * 8 + h);
                if (s == 0) {
                    const size_t idx = (bh * SEQ + nq) * DH + d;
                    g_qh[idx] = hi; g_ql[idx] = lo;
                } else if (s == 1) {
                    const size_t idx = (bh * SEQ + nq) * DH + d;
                    g_kh[idx] = hi; g_kl[idx] = lo;
                } else {
                    const size_t idx = (bh * DH + d) * SEQ + nq;  // transposed
                    g_vh[idx] = hi; g_vl[idx] = lo;
                }
            }
        }
    }
};

struct ProjEpilogue {
    float* out;
    const float* bias;
    __device__ __forceinline__ void operator()(
        int bm_, int bn_, const int* roff, const int* coff,
        float (&acc)[8][8]) const
    {
#pragma unroll
        for (int i = 0; i < 8; i++) {
            const int m = bm_ + roff[i];
#pragma unroll
            for (int j = 0; j < 8; j++) {
                const int n = bn_ + coff[j];
                out[(size_t)m * 256 + n] = acc[i][j] + bias[n];
            }
        }
    }
};

// ---------------------------------------------------------------------------
// 128x128x8 double-buffered NT GEMM, FFMA2 inner loop.
// ---------------------------------------------------------------------------
template <typename Epilogue>
__device__ __forceinline__ void gemm128x128(
    const float* __restrict__ A, const float* __restrict__ B,
    int bm, int bn, const Epilogue& epi)
{
    __shared__ __align__(16) float As[2][8][132];
    __shared__ __align__(16) float Bs[2][8][132];

    const int tid = threadIdx.x;
    const int lr = tid >> 1;
    const int lc = (tid & 1) * 4;
    const int tr0 = (tid >> 4) * 4;
    const int tc0 = (tid & 15) * 4;

    u64 acc2[8][4];
#pragma unroll
    for (int i = 0; i < 8; i++)
#pragma unroll
        for (int j = 0; j < 4; j++) acc2[i][j] = 0ull;

    float4 av = *(const float4*)&A[(size_t)(bm + lr) * 256 + lc];
    float4 bv = *(const float4*)&B[(size_t)(bn + lr) * 256 + lc];
    As[0][lc + 0][lr] = av.x; As[0][lc + 1][lr] = av.y;
    As[0][lc + 2][lr] = av.z; As[0][lc + 3][lr] = av.w;
    Bs[0][lc + 0][lr] = bv.x; Bs[0][lc + 1][lr] = bv.y;
    Bs[0][lc + 2][lr] = bv.z; Bs[0][lc + 3][lr] = bv.w;
    __syncthreads();

    int buf = 0;
    for (int k0 = 0; k0 < 256; k0 += 8) {
        const int nxt = k0 + 8;
        float4 an, bn4;
        if (nxt < 256) {
            an  = *(const float4*)&A[(size_t)(bm + lr) * 256 + nxt + lc];
            bn4 = *(const float4*)&B[(size_t)(bn + lr) * 256 + nxt + lc];
        }
#pragma unroll
        for (int kk = 0; kk < 8; kk++) {
            float4 a0 = *(const float4*)&As[buf][kk][tr0];
            float4 a1 = *(const float4*)&As[buf][kk][tr0 + 64];
            ulonglong2 bA = *(const ulonglong2*)&Bs[buf][kk][tc0];
            ulonglong2 bB = *(const ulonglong2*)&Bs[buf][kk][tc0 + 64];
            u64 b2[4] = {bA.x, bA.y, bB.x, bB.y};
            float ar[8] = {a0.x, a0.y, a0.z, a0.w, a1.x, a1.y, a1.z, a1.w};
            u64 as2[8];
#pragma unroll
            for (int i = 0; i < 8; i++) as2[i] = pk2(ar[i], ar[i]);
#pragma unroll
            for (int i = 0; i < 8; i++)
#pragma unroll
                for (int j = 0; j < 4; j++) ffma2(acc2[i][j], as2[i], b2[j]);
        }
        if (nxt < 256) {
            const int nb = buf ^ 1;
            As[nb][lc + 0][lr] = an.x;  As[nb][lc + 1][lr] = an.y;
            As[nb][lc + 2][lr] = an.z;  As[nb][lc + 3][lr] = an.w;
            Bs[nb][lc + 0][lr] = bn4.x; Bs[nb][lc + 1][lr] = bn4.y;
            Bs[nb][lc + 2][lr] = bn4.z; Bs[nb][lc + 3][lr] = bn4.w;
            buf = nb;
            __syncthreads();
        }
    }

    float acc[8][8];
#pragma unroll
    for (int i = 0; i < 8; i++)
#pragma unroll
        for (int j = 0; j < 4; j++) upk2(acc2[i][j], acc[i][2*j], acc[i][2*j + 1]);

    int roff[8], coff[8];
#pragma unroll
    for (int i = 0; i < 4; i++) {
        roff[i] = tr0 + i;      roff[i + 4] = tr0 + 64 + i;
        coff[i] = tc0 + i;      coff[i + 4] = tc0 + 64 + i;
    }
    epi(bm, bn, roff, coff, acc);
}

__global__ __launch_bounds__(256) void qkv_gemm_kernel(
    const float* __restrict__ X, const float* __restrict__ W)
{
    QkvEpilogue epi;
    gemm128x128(X, W, blockIdx.x * 128, blockIdx.y * 128, epi);
}

__global__ __launch_bounds__(256) void proj_gemm_kernel(
    const float* __restrict__ Wp, const float* __restrict__ bias,
    float* __restrict__ out)
{
    ProjEpilogue epi{out, bias};
    gemm128x128(g_att, Wp, blockIdx.x * 128, blockIdx.y * 128, epi);
}

// ---------------------------------------------------------------------------
// Tensor-core flash attention. Block = 4 warps x 16 query rows = 64 rows.
// Split bf16 (hi+lo): S = Qh*Kh + Qh*Kl + Ql*Kh; O += Ph*Vh + Ph*Vl + Pl*Vh.
// Fragment coords: g = lane>>2 (row g / g+8), t2 = (lane&3)*2 (cols t2,t2+1).
// ---------------------------------------------------------------------------
#define KST 40   // sKh/sKl row stride (bf16) -> conflict-free B-frag LDS
#define VST 72   // sVh/sVl row stride (bf16)

__global__ __launch_bounds__(128) void attn_kernel(const void* __restrict__ kpm)
{
    __shared__ __align__(16) __nv_bfloat16 sKh[64][KST];
    __shared__ __align__(16) __nv_bfloat16 sKl[64][KST];
    __shared__ __align__(16) __nv_bfloat16 sVh[32][VST];
    __shared__ __align__(16) __nv_bfloat16 sVl[32][VST];

    const int bh = blockIdx.y;
    const int b  = bh >> 3;
    const int h  = bh & 7;
    const int warp = threadIdx.x >> 5;
    const int lane = threadIdx.x & 31;
    const int g  = lane >> 2;
    const int t2 = (lane & 3) * 2;
    const int r0 = blockIdx.x * 64 + warp * 16;

    const int len = read_len(kpm, b);
    const float scale = 0.17677669529663687f;   // 1/sqrt(32)

    // Q fragments (2 k16 steps x 4 regs), hi and lo
    u32 qh[2][4], ql[2][4];
    {
        const __nv_bfloat16* qb_h = g_qh + ((size_t)bh * SEQ + r0) * DH;
        const __nv_bfloat16* qb_l = g_ql + ((size_t)bh * SEQ + r0) * DH;
#pragma unroll
        for (int kk = 0; kk < 2; kk++) {
            qh[kk][0] = *(const u32*)(qb_h + (size_t)g * DH       + kk*16 + t2);
            qh[kk][1] = *(const u32*)(qb_h + (size_t)(g+8) * DH   + kk*16 + t2);
            qh[kk][2] = *(const u32*)(qb_h + (size_t)g * DH       + kk*16 + t2 + 8);
            qh[kk][3] = *(const u32*)(qb_h + (size_t)(g+8) * DH   + kk*16 + t2 + 8);
            ql[kk][0] = *(const u32*)(qb_l + (size_t)g * DH       + kk*16 + t2);
            ql[kk][1] = *(const u32*)(qb_l + (size_t)(g+8) * DH   + kk*16 + t2);
            ql[kk][2] = *(const u32*)(qb_l + (size_t)g * DH       + kk*16 + t2 + 8);
            ql[kk][3] = *(const u32*)(qb_l + (size_t)(g+8) * DH   + kk*16 + t2 + 8);
        }
    }

    float O[4][4];
#pragma unroll
    for (int i = 0; i < 4; i++)
#pragma unroll
        for (int j = 0; j < 4; j++) O[i][j] = 0.f;
    float m0 = -CUDART_INF_F, m1 = -CUDART_INF_F;
    float l0 = 0.f, l1 = 0.f;

    const int ntiles = (len + 63) >> 6;
    for (int kt = 0; kt < ntiles; kt++) {
        const int k0 = kt * 64;
        __syncthreads();
        // fill K tiles (64x32) and V tiles (32x64, transposed source)
        {
            const __nv_bfloat16* gk_h = g_kh + ((size_t)bh * SEQ + k0) * DH;
            const __nv_bfloat16* gk_l = g_kl + ((size_t)bh * SEQ + k0) * DH;
#pragma unroll
            for (int it = 0; it < 4; it++) {
                const int idx = threadIdx.x + it * 128;   // 0..511
                const int row = idx >> 3;
                const int c   = (idx & 7) * 4;
                *(uint2*)&sKh[row][c] = *(const uint2*)(gk_h + (size_t)row * DH + c);
                *(uint2*)&sKl[row][c] = *(const uint2*)(gk_l + (size_t)row * DH + c);
            }
            const __nv_bfloat16* gv_h = g_vh + (size_t)bh * DH * SEQ + k0;
            const __nv_bfloat16* gv_l = g_vl + (size_t)bh * DH * SEQ + k0;
#pragma unroll
            for (int it = 0; it < 4; it++) {
                const int idx = threadIdx.x + it * 128;   // 0..511
                const int row = idx >> 4;                 // dh 0..31
                const int c   = (idx & 15) * 4;           // key 0..60
                *(uint2*)&sVh[row][c] = *(const uint2*)(gv_h + (size_t)row * SEQ + c);
                *(uint2*)&sVl[row][c] = *(const uint2*)(gv_l + (size_t)row * SEQ + c);
            }
        }
        __syncthreads();

        // ---- S = Q K^T (16 x 64), split 3-term ----
        float S[8][4];
#pragma unroll
        for (int nt = 0; nt < 8; nt++) {
            float* s = S[nt];
            s[0] = s[1] = s[2] = s[3] = 0.f;
            const int key = nt * 8 + g;
#pragma unroll
            for (int kk = 0; kk < 2; kk++) {
                const u32 bh0 = *(const u32*)&sKh[key][kk*16 + t2];
                const u32 bh1 = *(const u32*)&sKh[key][kk*16 + t2 + 8];
                const u32 bl0 = *(const u32*)&sKl[key][kk*16 + t2];
                const u32 bl1 = *(const u32*)&sKl[key][kk*16 + t2 + 8];
                mma16816(s, qh[kk], bh0, bh1);
                mma16816(s, qh[kk], bl0, bl1);
                mma16816(s, ql[kk], bh0, bh1);
            }
        }

        // ---- scale + mask ----
#pragma unroll
        for (int nt = 0; nt < 8; nt++) {
            const int kcol = k0 + nt * 8 + t2;
            const bool v0 = kcol < len, v1 = (kcol + 1) < len;
            S[nt][0] = v0 ? S[nt][0] * scale : -CUDART_INF_F;
            S[nt][1] = v1 ? S[nt][1] * scale : -CUDART_INF_F;
            S[nt][2] = v0 ? S[nt][2] * scale : -CUDART_INF_F;
            S[nt][3] = v1 ? S[nt][3] * scale : -CUDART_INF_F;
        }

        // ---- online softmax (rows g and g+8) ----
        float rm0 = -CUDART_INF_F, rm1 = -CUDART_INF_F;
#pragma unroll
        for (int nt = 0; nt < 8; nt++) {
            rm0 = fmaxf(rm0, fmaxf(S[nt][0], S[nt][1]));
            rm1 = fmaxf(rm1, fmaxf(S[nt][2], S[nt][3]));
        }
        rm0 = fmaxf(rm0, __shfl_xor_sync(0xffffffffu, rm0, 1));
        rm0 = fmaxf(rm0, __shfl_xor_sync(0xffffffffu, rm0, 2));
        rm1 = fmaxf(rm1, __shfl_xor_sync(0xffffffffu, rm1, 1));
        rm1 = fmaxf(rm1, __shfl_xor_sync(0xffffffffu, rm1, 2));

        const float nm0 = fmaxf(m0, rm0), nm1 = fmaxf(m1, rm1);
        const float cr0 = __expf(m0 - nm0), cr1 = __expf(m1 - nm1);
        m0 = nm0; m1 = nm1;
        l0 *= cr0; l1 *= cr1;
#pragma unroll
        for (int dn = 0; dn < 4; dn++) {
            O[dn][0] *= cr0; O[dn][1] *= cr0;
            O[dn][2] *= cr1; O[dn][3] *= cr1;
        }

        float ps0 = 0.f, ps1 = 0.f;
#pragma unroll
        for (int nt = 0; nt < 8; nt++) {
            S[nt][0] = __expf(S[nt][0] - m0);
            S[nt][1] = __expf(S[nt][1] - m0);
            S[nt][2] = __expf(S[nt][2] - m1);
            S[nt][3] = __expf(S[nt][3] - m1);
            ps0 += S[nt][0] + S[nt][1];
            ps1 += S[nt][2] + S[nt][3];
        }
        ps0 += __shfl_xor_sync(0xffffffffu, ps0, 1);
        ps0 += __shfl_xor_sync(0xffffffffu, ps0, 2);
        ps1 += __shfl_xor_sync(0xffffffffu, ps1, 1);
        ps1 += __shfl_xor_sync(0xffffffffu, ps1, 2);
        l0 += ps0; l1 += ps1;

        // ---- O += P V (split 3-term) ----
#pragma unroll
        for (int kt8 = 0; kt8 < 8; kt8++) {
            const float p0 = S[kt8][0], p1 = S[kt8][1];
            const float p2 = S[kt8][2], p3 = S[kt8][3];
            const __nv_bfloat16 h0 = __float2bfloat16(p0);
            const __nv_bfloat16 h1 = __float2bfloat16(p1);
            const __nv_bfloat16 h2 = __float2bfloat16(p2);
            const __nv_bfloat16 h3 = __float2bfloat16(p3);
            const u32 ah0 = pack_bf(h0, h1);
            const u32 ah1 = pack_bf(h2, h3);
            const u32 al0 = pack_bf(__float2bfloat16(p0 - __bfloat162float(h0)),
                                    __float2bfloat16(p1 - __bfloat162float(h1)));
            const u32 al1 = pack_bf(__float2bfloat16(p2 - __bfloat162float(h2)),
                                    __float2bfloat16(p3 - __bfloat162float(h3)));
#pragma unroll
            for (int dn = 0; dn < 4; dn++) {
                const u32 vb_h = *(const u32*)&sVh[dn*8 + g][kt8*8 + t2];
                const u32 vb_l = *(const u32*)&sVl[dn*8 + g][kt8*8 + t2];
                mma16808(O[dn], ah0, ah1, vb_h);
                mma16808(O[dn], ah0, ah1, vb_l);
                mma16808(O[dn], al0, al1, vb_h);
            }
        }
    }

    // ---- normalize + store ----
    const float inv0 = 1.f / l0, inv1 = 1.f / l1;
    const int row0 = r0 + g, row1 = r0 + g + 8;
#pragma unroll
    for (int dn = 0; dn < 4; dn++) {
        const int col = h * 32 + dn * 8 + t2;
        float2 w0; w0.x = O[dn][0] * inv0; w0.y = O[dn][1] * inv0;
        float2 w1; w1.x = O[dn][2] * inv1; w1.y = O[dn][3] * inv1;
        *(float2*)&g_att[((size_t)(b * SEQ + row0)) * CH + col] = w0;
        *(float2*)&g_att[((size_t)(b * SEQ + row1)) * CH + col] = w1;
    }
}

// ---------------------------------------------------------------------------
// Launch: resolve inputs by element count.
// ---------------------------------------------------------------------------
extern "C" void kernel_launch(void* const* d_in, const int* in_sizes, int n_in,
                              void* d_out, int out_size)
{
    (void)out_size;
    const float* x = nullptr; const void* kpm = nullptr;
    const float* w_qkv = nullptr; const float* w_proj = nullptr;
    const float* b_proj = nullptr;

    for (int i = 0; i < n_in; i++) {
        switch (in_sizes[i]) {
            case 2097152: x      = (const float*)d_in[i]; break;
            case 4:       kpm    = d_in[i];               break;
            case 196608:  w_qkv  = (const float*)d_in[i]; break;
            case 65536:   w_proj = (const float*)d_in[i]; break;
            case 256:     b_proj = (const float*)d_in[i]; break;
            default: break;
        }
    }
    float* out = (float*)d_out;

    {   // QKV: 8192 x 768
        dim3 grid(M_ROWS / 128, 768 / 128);
        qkv_gemm_kernel<<<grid, 256>>>(x, w_qkv);
    }
    {   // attention: 64 q-rows per block, 4 warps
        dim3 grid(SEQ / 64, BH);
        attn_kernel<<<grid, 128>>>(kpm);
    }
    {   // proj: 8192 x 256
        dim3 grid(M_ROWS / 128, 256 / 128);
        proj_gemm_kernel<<<grid, 256>>>(w_proj, b_proj, out);
    }
}

// round 9
// speedup vs baseline: 2.4765x; 1.2951x over previous
#include <cuda_runtime.h>
#include <cuda_bf16.h>
#include <math_constants.h>

#define BATCH 4
#define SEQ   2048
#define CH    256
#define HEADS 8
#define DH    32
#define BH    (BATCH*HEADS)
#define M_ROWS (BATCH*SEQ)

typedef unsigned long long u64;
typedef unsigned int u32;
typedef __nv_bfloat16 bf16;

// ---------------------------------------------------------------------------
// Scratch: split-precision bf16 everything.
// ---------------------------------------------------------------------------
__device__ bf16 g_xh[M_ROWS * CH],  g_xl[M_ROWS * CH];       // x split
__device__ bf16 g_wqh[768 * CH],    g_wql[768 * CH];         // w_qkv split
__device__ bf16 g_wph[CH * CH],     g_wpl[CH * CH];          // w_proj split
__device__ bf16 g_qh[BH * SEQ * DH], g_ql[BH * SEQ * DH];
__device__ bf16 g_kh[BH * SEQ * DH], g_kl[BH * SEQ * DH];
__device__ bf16 g_vh[BH * DH * SEQ], g_vl[BH * DH * SEQ];    // [bh][dh][seq]
__device__ bf16 g_atth[M_ROWS * CH], g_attl[M_ROWS * CH];

// ---------------------------------------------------------------------------
// mma.sync wrappers (bf16 -> fp32 accum)
// ---------------------------------------------------------------------------
__device__ __forceinline__ void mma16816(float* d, const u32* a, u32 b0, u32 b1) {
    asm volatile(
        "mma.sync.aligned.m16n8k16.row.col.f32.bf16.bf16.f32 "
        "{%0,%1,%2,%3},{%4,%5,%6,%7},{%8,%9},{%0,%1,%2,%3};"
        : "+f"(d[0]), "+f"(d[1]), "+f"(d[2]), "+f"(d[3])
        : "r"(a[0]), "r"(a[1]), "r"(a[2]), "r"(a[3]), "r"(b0), "r"(b1));
}
__device__ __forceinline__ void mma16808(float* d, u32 a0, u32 a1, u32 b0) {
    asm volatile(
        "mma.sync.aligned.m16n8k8.row.col.f32.bf16.bf16.f32 "
        "{%0,%1,%2,%3},{%4,%5},{%6},{%0,%1,%2,%3};"
        : "+f"(d[0]), "+f"(d[1]), "+f"(d[2]), "+f"(d[3])
        : "r"(a0), "r"(a1), "r"(b0));
}
__device__ __forceinline__ u32 pack_bf(bf16 a, bf16 b) {
    return ((u32)__bfloat16_as_ushort(b) << 16) | (u32)__bfloat16_as_ushort(a);
}
__device__ __forceinline__ void split_f(float v, bf16& h, bf16& l) {
    h = __float2bfloat16(v);
    l = __float2bfloat16(v - __bfloat162float(h));
}

// Mask: lengths in [1,2048]; int64 vs int32 sniff (word[1]==0 => int64).
__device__ __forceinline__ int read_len(const void* kpm, int b)
{
    const int* p32 = (const int*)kpm;
    int len = (p32[1] == 0) ? (int)((const long long*)kpm)[b] : p32[b];
    if (len < 1)   len = 1;
    if (len > SEQ) len = SEQ;
    return len;
}

// ---------------------------------------------------------------------------
// Split kernel: fp32 -> (hi, lo) bf16, vectorized x4.
// ---------------------------------------------------------------------------
__global__ void split_kernel(const float* __restrict__ src,
                             bf16* __restrict__ hi, bf16* __restrict__ lo, int n4)
{
    const int i = blockIdx.x * blockDim.x + threadIdx.x;
    if (i >= n4) return;
    float4 v = ((const float4*)src)[i];
    bf16 h0, l0, h1, l1, h2, l2, h3, l3;
    split_f(v.x, h0, l0); split_f(v.y, h1, l1);
    split_f(v.z, h2, l2); split_f(v.w, h3, l3);
    ((uint2*)hi)[i] = make_uint2(pack_bf(h0, h1), pack_bf(h2, h3));
    ((uint2*)lo)[i] = make_uint2(pack_bf(l0, l1), pack_bf(l2, l3));
}

// ---------------------------------------------------------------------------
// Split-bf16 tensor-core NT GEMM: C[m,n] = sum_k A[m,k]*B[n,k], K=256.
// Block 128x128, 8 warps (4x2), warp tile 32x64, 3-term split.
// ---------------------------------------------------------------------------
#define AST 40

struct QkvEpi {
    __device__ __forceinline__ void operator()(int m, int n, float val) const {
        const int b  = m >> 11;
        const int nq = m & 2047;
        const int s  = n >> 8;
        const int h  = (n >> 5) & 7;
        const int d  = n & 31;
        bf16 hi, lo; split_f(val, hi, lo);
        const size_t bh = (size_t)(b * 8 + h);
        if (s == 0) {
            const size_t idx = (bh * SEQ + nq) * DH + d;
            g_qh[idx] = hi; g_ql[idx] = lo;
        } else if (s == 1) {
            const size_t idx = (bh * SEQ + nq) * DH + d;
            g_kh[idx] = hi; g_kl[idx] = lo;
        } else {
            const size_t idx = (bh * DH + d) * SEQ + nq;   // transposed
            g_vh[idx] = hi; g_vl[idx] = lo;
        }
    }
};

struct ProjEpi {
    float* out;
    const float* bias;
    __device__ __forceinline__ void operator()(int m, int n, float val) const {
        out[(size_t)m * CH + n] = val + bias[n];
    }
};

template <typename Epi>
__device__ __forceinline__ void mma_gemm(
    const bf16* __restrict__ Ah, const bf16* __restrict__ Al,
    const bf16* __restrict__ Bh, const bf16* __restrict__ Bl,
    int bm, int bn, const Epi& epi)
{
    __shared__ __align__(16) bf16 sAh[128][AST], sAl[128][AST];
    __shared__ __align__(16) bf16 sBh[128][AST], sBl[128][AST];

    const int tid  = threadIdx.x;
    const int warp = tid >> 5, lane = tid & 31;
    const int g = lane >> 2, t2 = (lane & 3) * 2;
    const int wm = warp >> 1, wn = warp & 1;

    float acc[2][8][4];
#pragma unroll
    for (int mf = 0; mf < 2; mf++)
#pragma unroll
        for (int nf = 0; nf < 8; nf++)
#pragma unroll
            for (int r = 0; r < 4; r++) acc[mf][nf][r] = 0.f;

    for (int k0 = 0; k0 < 256; k0 += 32) {
        __syncthreads();
#pragma unroll
        for (int i = 0; i < 4; i++) {
            const int idx = tid + i * 256;        // 0..1023
            const int row = idx >> 3;
            const int c   = (idx & 7) * 4;
            *(u64*)&sAh[row][c] = *(const u64*)&Ah[(size_t)(bm + row) * 256 + k0 + c];
            *(u64*)&sAl[row][c] = *(const u64*)&Al[(size_t)(bm + row) * 256 + k0 + c];
            *(u64*)&sBh[row][c] = *(const u64*)&Bh[(size_t)(bn + row) * 256 + k0 + c];
            *(u64*)&sBl[row][c] = *(const u64*)&Bl[(size_t)(bn + row) * 256 + k0 + c];
        }
        __syncthreads();

#pragma unroll
        for (int kk = 0; kk < 2; kk++) {
            u32 ah[2][4], al[2][4];
#pragma unroll
            for (int mf = 0; mf < 2; mf++) {
                const int rb = wm * 32 + mf * 16;
                ah[mf][0] = *(const u32*)&sAh[rb + g    ][kk*16 + t2];
                ah[mf][1] = *(const u32*)&sAh[rb + g + 8][kk*16 + t2];
                ah[mf][2] = *(const u32*)&sAh[rb + g    ][kk*16 + t2 + 8];
                ah[mf][3] = *(const u32*)&sAh[rb + g + 8][kk*16 + t2 + 8];
                al[mf][0] = *(const u32*)&sAl[rb + g    ][kk*16 + t2];
                al[mf][1] = *(const u32*)&sAl[rb + g + 8][kk*16 + t2];
                al[mf][2] = *(const u32*)&sAl[rb + g    ][kk*16 + t2 + 8];
                al[mf][3] = *(const u32*)&sAl[rb + g + 8][kk*16 + t2 + 8];
            }
#pragma unroll
            for (int nf = 0; nf < 8; nf++) {
                const int nb = wn * 64 + nf * 8 + g;
                const u32 bh0 = *(const u32*)&sBh[nb][kk*16 + t2];
                const u32 bh1 = *(const u32*)&sBh[nb][kk*16 + t2 + 8];
                const u32 bl0 = *(const u32*)&sBl[nb][kk*16 + t2];
                const u32 bl1 = *(const u32*)&sBl[nb][kk*16 + t2 + 8];
#pragma unroll
                for (int mf = 0; mf < 2; mf++) {
                    mma16816(acc[mf][nf], ah[mf], bh0, bh1);
                    mma16816(acc[mf][nf], ah[mf], bl0, bl1);
                    mma16816(acc[mf][nf], al[mf], bh0, bh1);
                }
            }
        }
    }

    // epilogue: d0,d1 -> row g, cols t2,t2+1 ; d2,d3 -> row g+8
#pragma unroll
    for (int mf = 0; mf < 2; mf++) {
        const int r0 = bm + wm * 32 + mf * 16 + g;
#pragma unroll
        for (int nf = 0; nf < 8; nf++) {
            const int c0 = bn + wn * 64 + nf * 8 + t2;
            epi(r0,     c0,     acc[mf][nf][0]);
            epi(r0,     c0 + 1, acc[mf][nf][1]);
            epi(r0 + 8, c0,     acc[mf][nf][2]);
            epi(r0 + 8, c0 + 1, acc[mf][nf][3]);
        }
    }
}

__global__ __launch_bounds__(256) void qkv_mma_kernel()
{
    QkvEpi epi;
    mma_gemm(g_xh, g_xl, g_wqh, g_wql, blockIdx.x * 128, blockIdx.y * 128, epi);
}

__global__ __launch_bounds__(256) void proj_mma_kernel(
    float* __restrict__ out, const float* __restrict__ bias)
{
    ProjEpi epi{out, bias};
    mma_gemm(g_atth, g_attl, g_wph, g_wpl, blockIdx.x * 128, blockIdx.y * 128, epi);
}

// ---------------------------------------------------------------------------
// Tensor-core flash attention (validated R8). Block = 4 warps x 16 q rows.
// Epilogue now writes split-bf16 att for the proj mma GEMM.
// ---------------------------------------------------------------------------
#define KST 40
#define VST 72

__global__ __launch_bounds__(128) void attn_kernel(const void* __restrict__ kpm)
{
    __shared__ __align__(16) bf16 sKh[64][KST];
    __shared__ __align__(16) bf16 sKl[64][KST];
    __shared__ __align__(16) bf16 sVh[32][VST];
    __shared__ __align__(16) bf16 sVl[32][VST];

    const int bh = blockIdx.y;
    const int b  = bh >> 3;
    const int h  = bh & 7;
    const int warp = threadIdx.x >> 5;
    const int lane = threadIdx.x & 31;
    const int g  = lane >> 2;
    const int t2 = (lane & 3) * 2;
    const int r0 = blockIdx.x * 64 + warp * 16;

    const int len = read_len(kpm, b);
    const float scale = 0.17677669529663687f;   // 1/sqrt(32)

    u32 qh[2][4], ql[2][4];
    {
        const bf16* qb_h = g_qh + ((size_t)bh * SEQ + r0) * DH;
        const bf16* qb_l = g_ql + ((size_t)bh * SEQ + r0) * DH;
#pragma unroll
        for (int kk = 0; kk < 2; kk++) {
            qh[kk][0] = *(const u32*)(qb_h + (size_t)g * DH     + kk*16 + t2);
            qh[kk][1] = *(const u32*)(qb_h + (size_t)(g+8) * DH + kk*16 + t2);
            qh[kk][2] = *(const u32*)(qb_h + (size_t)g * DH     + kk*16 + t2 + 8);
            qh[kk][3] = *(const u32*)(qb_h + (size_t)(g+8) * DH + kk*16 + t2 + 8);
            ql[kk][0] = *(const u32*)(qb_l + (size_t)g * DH     + kk*16 + t2);
            ql[kk][1] = *(const u32*)(qb_l + (size_t)(g+8) * DH + kk*16 + t2);
            ql[kk][2] = *(const u32*)(qb_l + (size_t)g * DH     + kk*16 + t2 + 8);
            ql[kk][3] = *(const u32*)(qb_l + (size_t)(g+8) * DH + kk*16 + t2 + 8);
        }
    }

    float O[4][4];
#pragma unroll
    for (int i = 0; i < 4; i++)
#pragma unroll
        for (int j = 0; j < 4; j++) O[i][j] = 0.f;
    float m0 = -CUDART_INF_F, m1 = -CUDART_INF_F;
    float l0 = 0.f, l1 = 0.f;

    const int ntiles = (len + 63) >> 6;
    for (int kt = 0; kt < ntiles; kt++) {
        const int k0 = kt * 64;
        __syncthreads();
        {
            const bf16* gk_h = g_kh + ((size_t)bh * SEQ + k0) * DH;
            const bf16* gk_l = g_kl + ((size_t)bh * SEQ + k0) * DH;
#pragma unroll
            for (int it = 0; it < 4; it++) {
                const int idx = threadIdx.x + it * 128;
                const int row = idx >> 3;
                const int c   = (idx & 7) * 4;
                *(uint2*)&sKh[row][c] = *(const uint2*)(gk_h + (size_t)row * DH + c);
                *(uint2*)&sKl[row][c] = *(const uint2*)(gk_l + (size_t)row * DH + c);
            }
            const bf16* gv_h = g_vh + (size_t)bh * DH * SEQ + k0;
            const bf16* gv_l = g_vl + (size_t)bh * DH * SEQ + k0;
#pragma unroll
            for (int it = 0; it < 4; it++) {
                const int idx = threadIdx.x + it * 128;
                const int row = idx >> 4;
                const int c   = (idx & 15) * 4;
                *(uint2*)&sVh[row][c] = *(const uint2*)(gv_h + (size_t)row * SEQ + c);
                *(uint2*)&sVl[row][c] = *(const uint2*)(gv_l + (size_t)row * SEQ + c);
            }
        }
        __syncthreads();

        float S[8][4];
#pragma unroll
        for (int nt = 0; nt < 8; nt++) {
            float* s = S[nt];
            s[0] = s[1] = s[2] = s[3] = 0.f;
            const int key = nt * 8 + g;
#pragma unroll
            for (int kk = 0; kk < 2; kk++) {
                const u32 bh0 = *(const u32*)&sKh[key][kk*16 + t2];
                const u32 bh1 = *(const u32*)&sKh[key][kk*16 + t2 + 8];
                const u32 bl0 = *(const u32*)&sKl[key][kk*16 + t2];
                const u32 bl1 = *(const u32*)&sKl[key][kk*16 + t2 + 8];
                mma16816(s, qh[kk], bh0, bh1);
                mma16816(s, qh[kk], bl0, bl1);
                mma16816(s, ql[kk], bh0, bh1);
            }
        }

#pragma unroll
        for (int nt = 0; nt < 8; nt++) {
            const int kcol = k0 + nt * 8 + t2;
            const bool v0 = kcol < len, v1 = (kcol + 1) < len;
            S[nt][0] = v0 ? S[nt][0] * scale : -CUDART_INF_F;
            S[nt][1] = v1 ? S[nt][1] * scale : -CUDART_INF_F;
            S[nt][2] = v0 ? S[nt][2] * scale : -CUDART_INF_F;
            S[nt][3] = v1 ? S[nt][3] * scale : -CUDART_INF_F;
        }

        float rm0 = -CUDART_INF_F, rm1 = -CUDART_INF_F;
#pragma unroll
        for (int nt = 0; nt < 8; nt++) {
            rm0 = fmaxf(rm0, fmaxf(S[nt][0], S[nt][1]));
            rm1 = fmaxf(rm1, fmaxf(S[nt][2], S[nt][3]));
        }
        rm0 = fmaxf(rm0, __shfl_xor_sync(0xffffffffu, rm0, 1));
        rm0 = fmaxf(rm0, __shfl_xor_sync(0xffffffffu, rm0, 2));
        rm1 = fmaxf(rm1, __shfl_xor_sync(0xffffffffu, rm1, 1));
        rm1 = fmaxf(rm1, __shfl_xor_sync(0xffffffffu, rm1, 2));

        const float nm0 = fmaxf(m0, rm0), nm1 = fmaxf(m1, rm1);
        const float cr0 = __expf(m0 - nm0), cr1 = __expf(m1 - nm1);
        m0 = nm0; m1 = nm1;
        l0 *= cr0; l1 *= cr1;
#pragma unroll
        for (int dn = 0; dn < 4; dn++) {
            O[dn][0] *= cr0; O[dn][1] *= cr0;
            O[dn][2] *= cr1; O[dn][3] *= cr1;
        }

        float ps0 = 0.f, ps1 = 0.f;
#pragma unroll
        for (int nt = 0; nt < 8; nt++) {
            S[nt][0] = __expf(S[nt][0] - m0);
            S[nt][1] = __expf(S[nt][1] - m0);
            S[nt][2] = __expf(S[nt][2] - m1);
            S[nt][3] = __expf(S[nt][3] - m1);
            ps0 += S[nt][0] + S[nt][1];
            ps1 += S[nt][2] + S[nt][3];
        }
        ps0 += __shfl_xor_sync(0xffffffffu, ps0, 1);
        ps0 += __shfl_xor_sync(0xffffffffu, ps0, 2);
        ps1 += __shfl_xor_sync(0xffffffffu, ps1, 1);
        ps1 += __shfl_xor_sync(0xffffffffu, ps1, 2);
        l0 += ps0; l1 += ps1;

#pragma unroll
        for (int kt8 = 0; kt8 < 8; kt8++) {
            const float p0 = S[kt8][0], p1 = S[kt8][1];
            const float p2 = S[kt8][2], p3 = S[kt8][3];
            bf16 h0, x0, h1, x1, h2, x2, h3, x3;
            split_f(p0, h0, x0); split_f(p1, h1, x1);
            split_f(p2, h2, x2); split_f(p3, h3, x3);
            const u32 ah0 = pack_bf(h0, h1);
            const u32 ah1 = pack_bf(h2, h3);
            const u32 al0 = pack_bf(x0, x1);
            const u32 al1 = pack_bf(x2, x3);
#pragma unroll
            for (int dn = 0; dn < 4; dn++) {
                const u32 vb_h = *(const u32*)&sVh[dn*8 + g][kt8*8 + t2];
                const u32 vb_l = *(const u32*)&sVl[dn*8 + g][kt8*8 + t2];
                mma16808(O[dn], ah0, ah1, vb_h);
                mma16808(O[dn], ah0, ah1, vb_l);
                mma16808(O[dn], al0, al1, vb_h);
            }
        }
    }

    // normalize + store split bf16 att
    const float inv0 = 1.f / l0, inv1 = 1.f / l1;
    const int row0 = r0 + g, row1 = r0 + g + 8;
#pragma unroll
    for (int dn = 0; dn < 4; dn++) {
        const int col = h * 32 + dn * 8 + t2;
        const size_t i0 = ((size_t)(b * SEQ + row0)) * CH + col;
        const size_t i1 = ((size_t)(b * SEQ + row1)) * CH + col;
        bf16 h0, x0, h1, x1;
        split_f(O[dn][0] * inv0, h0, x0); split_f(O[dn][1] * inv0, h1, x1);
        *(u32*)&g_atth[i0] = pack_bf(h0, h1);
        *(u32*)&g_attl[i0] = pack_bf(x0, x1);
        split_f(O[dn][2] * inv1, h0, x0); split_f(O[dn][3] * inv1, h1, x1);
        *(u32*)&g_atth[i1] = pack_bf(h0, h1);
        *(u32*)&g_attl[i1] = pack_bf(x0, x1);
    }
}

// ---------------------------------------------------------------------------
// Launch
// ---------------------------------------------------------------------------
extern "C" void kernel_launch(void* const* d_in, const int* in_sizes, int n_in,
                              void* d_out, int out_size)
{
    (void)out_size;
    const float* x = nullptr; const void* kpm = nullptr;
    const float* w_qkv = nullptr; const float* w_proj = nullptr;
    const float* b_proj = nullptr;

    for (int i = 0; i < n_in; i++) {
        switch (in_sizes[i]) {
            case 2097152: x      = (const float*)d_in[i]; break;
            case 4:       kpm    = d_in[i];               break;
            case 196608:  w_qkv  = (const float*)d_in[i]; break;
            case 65536:   w_proj = (const float*)d_in[i]; break;
            case 256:     b_proj = (const float*)d_in[i]; break;
            default: break;
        }
    }
    float* out = (float*)d_out;

    bf16 *xh, *xl, *wqh, *wql, *wph, *wpl;
    cudaGetSymbolAddress((void**)&xh,  g_xh);  cudaGetSymbolAddress((void**)&xl,  g_xl);
    cudaGetSymbolAddress((void**)&wqh, g_wqh); cudaGetSymbolAddress((void**)&wql, g_wql);
    cudaGetSymbolAddress((void**)&wph, g_wph); cudaGetSymbolAddress((void**)&wpl, g_wpl);

    split_kernel<<<(2097152/4 + 255)/256, 256>>>(x, xh, xl, 2097152/4);
    split_kernel<<<(196608/4  + 255)/256, 256>>>(w_qkv, wqh, wql, 196608/4);
    split_kernel<<<(65536/4   + 255)/256, 256>>>(w_proj, wph, wpl, 65536/4);

    {   // QKV mma: 8192 x 768
        dim3 grid(M_ROWS / 128, 768 / 128);
        qkv_mma_kernel<<<grid, 256>>>();
    }
    {   // attention
        dim3 grid(SEQ / 64, BH);
        attn_kernel<<<grid, 128>>>(kpm);
    }
    {   // proj mma: 8192 x 256
        dim3 grid(M_ROWS / 128, 256 / 128);
        proj_mma_kernel<<<grid, 256>>>(out, b_proj);
    }
}

// round 11
// speedup vs baseline: 2.5489x; 1.0292x over previous
#include <cuda_runtime.h>
#include <cuda_bf16.h>
#include <math_constants.h>

#define BATCH 4
#define SEQ   2048
#define CH    256
#define HEADS 8
#define DH    32
#define BH    (BATCH*HEADS)
#define M_ROWS (BATCH*SEQ)

typedef unsigned long long u64;
typedef unsigned int u32;
typedef __nv_bfloat16 bf16;

// ---------------------------------------------------------------------------
// Scratch: split-precision bf16 everything.
// ---------------------------------------------------------------------------
__device__ bf16 g_xh[M_ROWS * CH],  g_xl[M_ROWS * CH];
__device__ bf16 g_wqh[768 * CH],    g_wql[768 * CH];
__device__ bf16 g_wph[CH * CH],     g_wpl[CH * CH];
__device__ bf16 g_qh[BH * SEQ * DH], g_ql[BH * SEQ * DH];
__device__ bf16 g_kh[BH * SEQ * DH], g_kl[BH * SEQ * DH];
__device__ bf16 g_vh[BH * DH * SEQ], g_vl[BH * DH * SEQ];    // [bh][dh][seq]
__device__ bf16 g_atth[M_ROWS * CH], g_attl[M_ROWS * CH];

// ---------------------------------------------------------------------------
// mma.sync wrappers (bf16 -> fp32 accum)
// ---------------------------------------------------------------------------
__device__ __forceinline__ void mma16816(float* d, const u32* a, u32 b0, u32 b1) {
    asm volatile(
        "mma.sync.aligned.m16n8k16.row.col.f32.bf16.bf16.f32 "
        "{%0,%1,%2,%3},{%4,%5,%6,%7},{%8,%9},{%0,%1,%2,%3};"
        : "+f"(d[0]), "+f"(d[1]), "+f"(d[2]), "+f"(d[3])
        : "r"(a[0]), "r"(a[1]), "r"(a[2]), "r"(a[3]), "r"(b0), "r"(b1));
}
__device__ __forceinline__ void mma16808(float* d, u32 a0, u32 a1, u32 b0) {
    asm volatile(
        "mma.sync.aligned.m16n8k8.row.col.f32.bf16.bf16.f32 "
        "{%0,%1,%2,%3},{%4,%5},{%6},{%0,%1,%2,%3};"
        : "+f"(d[0]), "+f"(d[1]), "+f"(d[2]), "+f"(d[3])
        : "r"(a0), "r"(a1), "r"(b0));
}
__device__ __forceinline__ u32 pack_bf(bf16 a, bf16 b) {
    return ((u32)__bfloat16_as_ushort(b) << 16) | (u32)__bfloat16_as_ushort(a);
}
__device__ __forceinline__ void split_f(float v, bf16& h, bf16& l) {
    h = __float2bfloat16(v);
    l = __float2bfloat16(v - __bfloat162float(h));
}

// Mask: lengths in [1,2048]; int64 vs int32 sniff (word[1]==0 => int64).
__device__ __forceinline__ int read_len(const void* kpm, int b)
{
    const int* p32 = (const int*)kpm;
    int len = (p32[1] == 0) ? (int)((const long long*)kpm)[b] : p32[b];
    if (len < 1)   len = 1;
    if (len > SEQ) len = SEQ;
    return len;
}

// ---------------------------------------------------------------------------
// Split kernel: fp32 -> (hi, lo) bf16, vectorized x4.
// ---------------------------------------------------------------------------
__global__ void split_kernel(const float* __restrict__ src,
                             bf16* __restrict__ hi, bf16* __restrict__ lo, int n4)
{
    const int i = blockIdx.x * blockDim.x + threadIdx.x;
    if (i >= n4) return;
    float4 v = ((const float4*)src)[i];
    bf16 h0, l0, h1, l1, h2, l2, h3, l3;
    split_f(v.x, h0, l0); split_f(v.y, h1, l1);
    split_f(v.z, h2, l2); split_f(v.w, h3, l3);
    ((uint2*)hi)[i] = make_uint2(pack_bf(h0, h1), pack_bf(h2, h3));
    ((uint2*)lo)[i] = make_uint2(pack_bf(l0, l1), pack_bf(l2, l3));
}

// ---------------------------------------------------------------------------
// Split-bf16 tensor-core NT GEMM with gmem->reg software pipelining.
// Block 128x128, 8 warps (4x2), warp tile 32x64, 3-term split, K=256, step 32.
// ---------------------------------------------------------------------------
#define AST 40

struct QkvEpi {
    __device__ __forceinline__ void operator()(int m, int n, float val) const {
        const int b  = m >> 11;
        const int nq = m & 2047;
        const int s  = n >> 8;
        const int h  = (n >> 5) & 7;
        const int d  = n & 31;
        bf16 hi, lo; split_f(val, hi, lo);
        const size_t bh = (size_t)(b * 8 + h);
        if (s == 0) {
            const size_t idx = (bh * SEQ + nq) * DH + d;
            g_qh[idx] = hi; g_ql[idx] = lo;
        } else if (s == 1) {
            const size_t idx = (bh * SEQ + nq) * DH + d;
            g_kh[idx] = hi; g_kl[idx] = lo;
        } else {
            const size_t idx = (bh * DH + d) * SEQ + nq;   // transposed
            g_vh[idx] = hi; g_vl[idx] = lo;
        }
    }
};

struct ProjEpi {
    float* out;
    const float* bias;
    __device__ __forceinline__ void operator()(int m, int n, float val) const {
        out[(size_t)m * CH + n] = val + bias[n];
    }
};

template <typename Epi>
__device__ __forceinline__ void mma_gemm(
    const bf16* __restrict__ Ah, const bf16* __restrict__ Al,
    const bf16* __restrict__ Bh, const bf16* __restrict__ Bl,
    int bm, int bn, const Epi& epi)
{
    __shared__ __align__(16) bf16 sAh[128][AST], sAl[128][AST];
    __shared__ __align__(16) bf16 sBh[128][AST], sBl[128][AST];

    const int tid  = threadIdx.x;
    const int warp = tid >> 5, lane = tid & 31;
    const int g = lane >> 2, t2 = (lane & 3) * 2;
    const int wm = warp >> 1, wn = warp & 1;

    // per-thread load coords (4 chunks of 256 threads covering 128x32)
    int lrow[4], lcol[4];
#pragma unroll
    for (int i = 0; i < 4; i++) {
        const int idx = tid + i * 256;
        lrow[i] = idx >> 3;
        lcol[i] = (idx & 7) * 4;
    }

    float acc[2][8][4];
#pragma unroll
    for (int mf = 0; mf < 2; mf++)
#pragma unroll
        for (int nf = 0; nf < 8; nf++)
#pragma unroll
            for (int r = 0; r < 4; r++) acc[mf][nf][r] = 0.f;

    // prologue: prefetch k-step 0
    u64 rah[4], ral[4], rbh[4], rbl[4];
#pragma unroll
    for (int i = 0; i < 4; i++) {
        rah[i] = *(const u64*)&Ah[(size_t)(bm + lrow[i]) * 256 + lcol[i]];
        ral[i] = *(const u64*)&Al[(size_t)(bm + lrow[i]) * 256 + lcol[i]];
        rbh[i] = *(const u64*)&Bh[(size_t)(bn + lrow[i]) * 256 + lcol[i]];
        rbl[i] = *(const u64*)&Bl[(size_t)(bn + lrow[i]) * 256 + lcol[i]];
    }

    for (int ks = 0; ks < 8; ks++) {
        // store current regs -> smem
#pragma unroll
        for (int i = 0; i < 4; i++) {
            *(u64*)&sAh[lrow[i]][lcol[i]] = rah[i];
            *(u64*)&sAl[lrow[i]][lcol[i]] = ral[i];
            *(u64*)&sBh[lrow[i]][lcol[i]] = rbh[i];
            *(u64*)&sBl[lrow[i]][lcol[i]] = rbl[i];
        }
        __syncthreads();

        // prefetch next k-step (overlaps with mma below)
        if (ks < 7) {
            const int k0 = (ks + 1) * 32;
#pragma unroll
            for (int i = 0; i < 4; i++) {
                rah[i] = *(const u64*)&Ah[(size_t)(bm + lrow[i]) * 256 + k0 + lcol[i]];
                ral[i] = *(const u64*)&Al[(size_t)(bm + lrow[i]) * 256 + k0 + lcol[i]];
                rbh[i] = *(const u64*)&Bh[(size_t)(bn + lrow[i]) * 256 + k0 + lcol[i]];
                rbl[i] = *(const u64*)&Bl[(size_t)(bn + lrow[i]) * 256 + k0 + lcol[i]];
            }
        }

#pragma unroll
        for (int kk = 0; kk < 2; kk++) {
            u32 ah[2][4], al[2][4];
#pragma unroll
            for (int mf = 0; mf < 2; mf++) {
                const int rb = wm * 32 + mf * 16;
                ah[mf][0] = *(const u32*)&sAh[rb + g    ][kk*16 + t2];
                ah[mf][1] = *(const u32*)&sAh[rb + g + 8][kk*16 + t2];
                ah[mf][2] = *(const u32*)&sAh[rb + g    ][kk*16 + t2 + 8];
                ah[mf][3] = *(const u32*)&sAh[rb + g + 8][kk*16 + t2 + 8];
                al[mf][0] = *(const u32*)&sAl[rb + g    ][kk*16 + t2];
                al[mf][1] = *(const u32*)&sAl[rb + g + 8][kk*16 + t2];
                al[mf][2] = *(const u32*)&sAl[rb + g    ][kk*16 + t2 + 8];
                al[mf][3] = *(const u32*)&sAl[rb + g + 8][kk*16 + t2 + 8];
            }
#pragma unroll
            for (int nf = 0; nf < 8; nf++) {
                const int nb = wn * 64 + nf * 8 + g;
                const u32 bh0 = *(const u32*)&sBh[nb][kk*16 + t2];
                const u32 bh1 = *(const u32*)&sBh[nb][kk*16 + t2 + 8];
                const u32 bl0 = *(const u32*)&sBl[nb][kk*16 + t2];
                const u32 bl1 = *(const u32*)&sBl[nb][kk*16 + t2 + 8];
#pragma unroll
                for (int mf = 0; mf < 2; mf++) {
                    mma16816(acc[mf][nf], ah[mf], bh0, bh1);
                    mma16816(acc[mf][nf], ah[mf], bl0, bl1);
                    mma16816(acc[mf][nf], al[mf], bh0, bh1);
                }
            }
        }
        __syncthreads();
    }

#pragma unroll
    for (int mf = 0; mf < 2; mf++) {
        const int r0 = bm + wm * 32 + mf * 16 + g;
#pragma unroll
        for (int nf = 0; nf < 8; nf++) {
            const int c0 = bn + wn * 64 + nf * 8 + t2;
            epi(r0,     c0,     acc[mf][nf][0]);
            epi(r0,     c0 + 1, acc[mf][nf][1]);
            epi(r0 + 8, c0,     acc[mf][nf][2]);
            epi(r0 + 8, c0 + 1, acc[mf][nf][3]);
        }
    }
}

__global__ __launch_bounds__(256) void qkv_mma_kernel()
{
    QkvEpi epi;
    mma_gemm(g_xh, g_xl, g_wqh, g_wql, blockIdx.x * 128, blockIdx.y * 128, epi);
}

__global__ __launch_bounds__(256) void proj_mma_kernel(
    float* __restrict__ out, const float* __restrict__ bias)
{
    ProjEpi epi{out, bias};
    mma_gemm(g_atth, g_attl, g_wph, g_wpl, blockIdx.x * 128, blockIdx.y * 128, epi);
}

// ---------------------------------------------------------------------------
// Tensor-core flash attention, gmem->reg prefetch of next K/V tile.
// ---------------------------------------------------------------------------
#define KST 40
#define VST 72

__device__ __forceinline__ void attn_tile_load(
    int tid, int bh, int k0,
    uint2* rKh, uint2* rKl, uint2* rVh, uint2* rVl)
{
    const bf16* gk_h = g_kh + ((size_t)bh * SEQ + k0) * DH;
    const bf16* gk_l = g_kl + ((size_t)bh * SEQ + k0) * DH;
    const bf16* gv_h = g_vh + (size_t)bh * DH * SEQ + k0;
    const bf16* gv_l = g_vl + (size_t)bh * DH * SEQ + k0;
#pragma unroll
    for (int it = 0; it < 4; it++) {
        const int idx = tid + it * 128;
        const int kr = idx >> 3, kc = (idx & 7) * 4;
        rKh[it] = *(const uint2*)(gk_h + (size_t)kr * DH + kc);
        rKl[it] = *(const uint2*)(gk_l + (size_t)kr * DH + kc);
        const int vr = idx >> 4, vc = (idx & 15) * 4;
        rVh[it] = *(const uint2*)(gv_h + (size_t)vr * SEQ + vc);
        rVl[it] = *(const uint2*)(gv_l + (size_t)vr * SEQ + vc);
    }
}

__global__ __launch_bounds__(128) void attn_kernel(const void* __restrict__ kpm)
{
    __shared__ __align__(16) bf16 sKh[64][KST];
    __shared__ __align__(16) bf16 sKl[64][KST];
    __shared__ __align__(16) bf16 sVh[32][VST];
    __shared__ __align__(16) bf16 sVl[32][VST];

    const int bh = blockIdx.y;
    const int b  = bh >> 3;
    const int h  = bh & 7;
    const int tid  = threadIdx.x;
    const int warp = tid >> 5;
    const int lane = tid & 31;
    const int g  = lane >> 2;
    const int t2 = (lane & 3) * 2;
    const int r0 = blockIdx.x * 64 + warp * 16;

    const int len = read_len(kpm, b);
    const float scale = 0.17677669529663687f;   // 1/sqrt(32)

    u32 qh[2][4], ql[2][4];
    {
        const bf16* qb_h = g_qh + ((size_t)bh * SEQ + r0) * DH;
        const bf16* qb_l = g_ql + ((size_t)bh * SEQ + r0) * DH;
#pragma unroll
        for (int kk = 0; kk < 2; kk++) {
            qh[kk][0] = *(const u32*)(qb_h + (size_t)g * DH     + kk*16 + t2);
            qh[kk][1] = *(const u32*)(qb_h + (size_t)(g+8) * DH + kk*16 + t2);
            qh[kk][2] = *(const u32*)(qb_h + (size_t)g * DH     + kk*16 + t2 + 8);
            qh[kk][3] = *(const u32*)(qb_h + (size_t)(g+8) * DH + kk*16 + t2 + 8);
            ql[kk][0] = *(const u32*)(qb_l + (size_t)g * DH     + kk*16 + t2);
            ql[kk][1] = *(const u32*)(qb_l + (size_t)(g+8) * DH + kk*16 + t2);
            ql[kk][2] = *(const u32*)(qb_l + (size_t)g * DH     + kk*16 + t2 + 8);
            ql[kk][3] = *(const u32*)(qb_l + (size_t)(g+8) * DH + kk*16 + t2 + 8);
        }
    }

    float O[4][4];
#pragma unroll
    for (int i = 0; i < 4; i++)
#pragma unroll
        for (int j = 0; j < 4; j++) O[i][j] = 0.f;
    float m0 = -CUDART_INF_F, m1 = -CUDART_INF_F;
    float l0 = 0.f, l1 = 0.f;

    // per-thread smem store coords
    int kr[4], kc[4], vr[4], vc[4];
#pragma unroll
    for (int it = 0; it < 4; it++) {
        const int idx = tid + it * 128;
        kr[it] = idx >> 3;  kc[it] = (idx & 7) * 4;
        vr[it] = idx >> 4;  vc[it] = (idx & 15) * 4;
    }

    uint2 rKh[4], rKl[4], rVh[4], rVl[4];
    attn_tile_load(tid, bh, 0, rKh, rKl, rVh, rVl);

    const int ntiles = (len + 63) >> 6;
    for (int kt = 0; kt < ntiles; kt++) {
        const int k0 = kt * 64;
        // store prefetched tile to smem
#pragma unroll
        for (int it = 0; it < 4; it++) {
            *(uint2*)&sKh[kr[it]][kc[it]] = rKh[it];
            *(uint2*)&sKl[kr[it]][kc[it]] = rKl[it];
            *(uint2*)&sVh[vr[it]][vc[it]] = rVh[it];
            *(uint2*)&sVl[vr[it]][vc[it]] = rVl[it];
        }
        __syncthreads();

        // prefetch next tile (overlaps with compute below)
        if (kt + 1 < ntiles)
            attn_tile_load(tid, bh, k0 + 64, rKh, rKl, rVh, rVl);

        float S[8][4];
#pragma unroll
        for (int nt = 0; nt < 8; nt++) {
            float* s = S[nt];
            s[0] = s[1] = s[2] = s[3] = 0.f;
            const int key = nt * 8 + g;
#pragma unroll
            for (int kk = 0; kk < 2; kk++) {
                const u32 bh0 = *(const u32*)&sKh[key][kk*16 + t2];
                const u32 bh1 = *(const u32*)&sKh[key][kk*16 + t2 + 8];
                const u32 bl0 = *(const u32*)&sKl[key][kk*16 + t2];
                const u32 bl1 = *(const u32*)&sKl[key][kk*16 + t2 + 8];
                mma16816(s, qh[kk], bh0, bh1);
                mma16816(s, qh[kk], bl0, bl1);
                mma16816(s, ql[kk], bh0, bh1);
            }
        }

#pragma unroll
        for (int nt = 0; nt < 8; nt++) {
            const int kcol = k0 + nt * 8 + t2;
            const bool v0 = kcol < len, v1 = (kcol + 1) < len;
            S[nt][0] = v0 ? S[nt][0] * scale : -CUDART_INF_F;
            S[nt][1] = v1 ? S[nt][1] * scale : -CUDART_INF_F;
            S[nt][2] = v0 ? S[nt][2] * scale : -CUDART_INF_F;
            S[nt][3] = v1 ? S[nt][3] * scale : -CUDART_INF_F;
        }

        float rm0 = -CUDART_INF_F, rm1 = -CUDART_INF_F;
#pragma unroll
        for (int nt = 0; nt < 8; nt++) {
            rm0 = fmaxf(rm0, fmaxf(S[nt][0], S[nt][1]));
            rm1 = fmaxf(rm1, fmaxf(S[nt][2], S[nt][3]));
        }
        rm0 = fmaxf(rm0, __shfl_xor_sync(0xffffffffu, rm0, 1));
        rm0 = fmaxf(rm0, __shfl_xor_sync(0xffffffffu, rm0, 2));
        rm1 = fmaxf(rm1, __shfl_xor_sync(0xffffffffu, rm1, 1));
        rm1 = fmaxf(rm1, __shfl_xor_sync(0xffffffffu, rm1, 2));

        const float nm0 = fmaxf(m0, rm0), nm1 = fmaxf(m1, rm1);
        const float cr0 = __expf(m0 - nm0), cr1 = __expf(m1 - nm1);
        m0 = nm0; m1 = nm1;
        l0 *= cr0; l1 *= cr1;
#pragma unroll
        for (int dn = 0; dn < 4; dn++) {
            O[dn][0] *= cr0; O[dn][1] *= cr0;
            O[dn][2] *= cr1; O[dn][3] *= cr1;
        }

        float ps0 = 0.f, ps1 = 0.f;
#pragma unroll
        for (int nt = 0; nt < 8; nt++) {
            S[nt][0] = __expf(S[nt][0] - m0);
            S[nt][1] = __expf(S[nt][1] - m0);
            S[nt][2] = __expf(S[nt][2] - m1);
            S[nt][3] = __expf(S[nt][3] - m1);
            ps0 += S[nt][0] + S[nt][1];
            ps1 += S[nt][2] + S[nt][3];
        }
        ps0 += __shfl_xor_sync(0xffffffffu, ps0, 1);
        ps0 += __shfl_xor_sync(0xffffffffu, ps0, 2);
        ps1 += __shfl_xor_sync(0xffffffffu, ps1, 1);
        ps1 += __shfl_xor_sync(0xffffffffu, ps1, 2);
        l0 += ps0; l1 += ps1;

#pragma unroll
        for (int kt8 = 0; kt8 < 8; kt8++) {
            const float p0 = S[kt8][0], p1 = S[kt8][1];
            const float p2 = S[kt8][2], p3 = S[kt8][3];
            bf16 h0, x0, h1, x1, h2, x2, h3, x3;
            split_f(p0, h0, x0); split_f(p1, h1, x1);
            split_f(p2, h2, x2); split_f(p3, h3, x3);
            const u32 ah0 = pack_bf(h0, h1);
            const u32 ah1 = pack_bf(h2, h3);
            const u32 al0 = pack_bf(x0, x1);
            const u32 al1 = pack_bf(x2, x3);
#pragma unroll
            for (int dn = 0; dn < 4; dn++) {
                const u32 vb_h = *(const u32*)&sVh[dn*8 + g][kt8*8 + t2];
                const u32 vb_l = *(const u32*)&sVl[dn*8 + g][kt8*8 + t2];
                mma16808(O[dn], ah0, ah1, vb_h);
                mma16808(O[dn], ah0, ah1, vb_l);
                mma16808(O[dn], al0, al1, vb_h);
            }
        }
        __syncthreads();
    }

    // normalize + store split bf16 att
    const float inv0 = 1.f / l0, inv1 = 1.f / l1;
    const int row0 = r0 + g, row1 = r0 + g + 8;
#pragma unroll
    for (int dn = 0; dn < 4; dn++) {
        const int col = h * 32 + dn * 8 + t2;
        const size_t i0 = ((size_t)(b * SEQ + row0)) * CH + col;
        const size_t i1 = ((size_t)(b * SEQ + row1)) * CH + col;
        bf16 h0, x0, h1, x1;
        split_f(O[dn][0] * inv0, h0, x0); split_f(O[dn][1] * inv0, h1, x1);
        *(u32*)&g_atth[i0] = pack_bf(h0, h1);
        *(u32*)&g_attl[i0] = pack_bf(x0, x1);
        split_f(O[dn][2] * inv1, h0, x0); split_f(O[dn][3] * inv1, h1, x1);
        *(u32*)&g_atth[i1] = pack_bf(h0, h1);
        *(u32*)&g_attl[i1] = pack_bf(x0, x1);
    }
}

// ---------------------------------------------------------------------------
// Launch
// ---------------------------------------------------------------------------
extern "C" void kernel_launch(void* const* d_in, const int* in_sizes, int n_in,
                              void* d_out, int out_size)
{
    (void)out_size;
    const float* x = nullptr; const void* kpm = nullptr;
    const float* w_qkv = nullptr; const float* w_proj = nullptr;
    const float* b_proj = nullptr;

    for (int i = 0; i < n_in; i++) {
        switch (in_sizes[i]) {
            case 2097152: x      = (const float*)d_in[i]; break;
            case 4:       kpm    = d_in[i];               break;
            case 196608:  w_qkv  = (const float*)d_in[i]; break;
            case 65536:   w_proj = (const float*)d_in[i]; break;
            case 256:     b_proj = (const float*)d_in[i]; break;
            default: break;
        }
    }
    float* out = (float*)d_out;

    bf16 *xh, *xl, *wqh, *wql, *wph, *wpl;
    cudaGetSymbolAddress((void**)&xh,  g_xh);  cudaGetSymbolAddress((void**)&xl,  g_xl);
    cudaGetSymbolAddress((void**)&wqh, g_wqh); cudaGetSymbolAddress((void**)&wql, g_wql);
    cudaGetSymbolAddress((void**)&wph, g_wph); cudaGetSymbolAddress((void**)&wpl, g_wpl);

    split_kernel<<<(2097152/4 + 255)/256, 256>>>(x, xh, xl, 2097152/4);
    split_kernel<<<(196608/4  + 255)/256, 256>>>(w_qkv, wqh, wql, 196608/4);
    split_kernel<<<(65536/4   + 255)/256, 256>>>(w_proj, wph, wpl, 65536/4);

    {   // QKV mma: 8192 x 768
        dim3 grid(M_ROWS / 128, 768 / 128);
        qkv_mma_kernel<<<grid, 256>>>();
    }
    {   // attention
        dim3 grid(SEQ / 64, BH);
        attn_kernel<<<grid, 128>>>(kpm);
    }
    {   // proj mma: 8192 x 256
        dim3 grid(M_ROWS / 128, 256 / 128);
        proj_mma_kernel<<<grid, 256>>>(out, b_proj);
    }
}

// round 12
// speedup vs baseline: 3.3010x; 1.2951x over previous
#include <cuda_runtime.h>
#include <cuda_bf16.h>
#include <math_constants.h>

#define BATCH 4
#define SEQ   2048
#define CH    256
#define HEADS 8
#define DH    32
#define BH    (BATCH*HEADS)
#define M_ROWS (BATCH*SEQ)

typedef unsigned int u32;

// ---------------------------------------------------------------------------
// Scratch (fp32, tf32-rounded values)
// ---------------------------------------------------------------------------
__device__ float g_xr[M_ROWS * CH];     // x rounded
__device__ float g_wqr[768 * CH];       // w_qkv rounded
__device__ float g_wpr[CH * CH];        // w_proj rounded
__device__ float g_q[BH * SEQ * DH];
__device__ float g_k[BH * SEQ * DH];
__device__ float g_v[BH * DH * SEQ];    // transposed [bh][dh][seq]
__device__ float g_att[M_ROWS * CH];

// ---------------------------------------------------------------------------
// tf32 helpers
// ---------------------------------------------------------------------------
__device__ __forceinline__ u32 tf32r(float x) {
    u32 r; asm("cvt.rna.tf32.f32 %0,%1;" : "=r"(r) : "f"(x)); return r;
}
__device__ __forceinline__ float tf32f(float x) {
    return __uint_as_float(tf32r(x));
}
// D += A*B, m16n8k8 tf32. a: 4 regs, b: 2 regs (fp32 bit patterns, pre-rounded)
__device__ __forceinline__ void mma_tf32(float* d, const float* a, float b0, float b1) {
    asm volatile(
        "mma.sync.aligned.m16n8k8.row.col.f32.tf32.tf32.f32 "
        "{%0,%1,%2,%3},{%4,%5,%6,%7},{%8,%9},{%0,%1,%2,%3};"
        : "+f"(d[0]), "+f"(d[1]), "+f"(d[2]), "+f"(d[3])
        : "r"(__float_as_uint(a[0])), "r"(__float_as_uint(a[1])),
          "r"(__float_as_uint(a[2])), "r"(__float_as_uint(a[3])),
          "r"(__float_as_uint(b0)), "r"(__float_as_uint(b1)));
}

// Mask: lengths in [1,2048]; int64 vs int32 sniff (word[1]==0 => int64).
__device__ __forceinline__ int read_len(const void* kpm, int b)
{
    const int* p32 = (const int*)kpm;
    int len = (p32[1] == 0) ? (int)((const long long*)kpm)[b] : p32[b];
    if (len < 1)   len = 1;
    if (len > SEQ) len = SEQ;
    return len;
}

// ---------------------------------------------------------------------------
// Round fp32 -> tf32-valued fp32, vectorized x4.
// ---------------------------------------------------------------------------
__global__ void round_kernel(const float* __restrict__ src,
                             float* __restrict__ dst, int n4)
{
    const int i = blockIdx.x * blockDim.x + threadIdx.x;
    if (i >= n4) return;
    float4 v = ((const float4*)src)[i];
    v.x = tf32f(v.x); v.y = tf32f(v.y); v.z = tf32f(v.z); v.w = tf32f(v.w);
    ((float4*)dst)[i] = v;
}

// ---------------------------------------------------------------------------
// TF32 tensor-core NT GEMM: C[m,n] = sum_k A[m,k]*B[n,k], K=256.
// Block 128x128, 8 warps (4x2), warp tile 32x64, k-step 32 (4 x k8).
// ---------------------------------------------------------------------------
#define AST 36   // 32 + 4 pad (floats)

struct QkvEpi {
    __device__ __forceinline__ void operator()(int m, int n, float val) const {
        const int b  = m >> 11;
        const int nq = m & 2047;
        const int s  = n >> 8;        // 0=q 1=k 2=v
        const int h  = (n >> 5) & 7;
        const int d  = n & 31;
        const float rv = tf32f(val);
        const size_t bh = (size_t)(b * 8 + h);
        if (s == 0)      g_q[(bh * SEQ + nq) * DH + d] = rv;
        else if (s == 1) g_k[(bh * SEQ + nq) * DH + d] = rv;
        else             g_v[(bh * DH + d) * SEQ + nq] = rv;   // transposed
    }
};

struct ProjEpi {
    float* out;
    const float* bias;
    __device__ __forceinline__ void operator()(int m, int n, float val) const {
        out[(size_t)m * CH + n] = val + bias[n];
    }
};

template <typename Epi>
__device__ __forceinline__ void mma_gemm(
    const float* __restrict__ A, const float* __restrict__ B,
    int bm, int bn, const Epi& epi)
{
    __shared__ __align__(16) float sA[128][AST];
    __shared__ __align__(16) float sB[128][AST];

    const int tid  = threadIdx.x;
    const int warp = tid >> 5, lane = tid & 31;
    const int g = lane >> 2, tq = lane & 3, t2 = tq * 2;
    const int wm = warp >> 1, wn = warp & 1;

    float acc[2][8][4];
#pragma unroll
    for (int mf = 0; mf < 2; mf++)
#pragma unroll
        for (int nf = 0; nf < 8; nf++)
#pragma unroll
            for (int r = 0; r < 4; r++) acc[mf][nf][r] = 0.f;

    for (int ks = 0; ks < 8; ks++) {
        const int k0 = ks * 32;
        __syncthreads();
#pragma unroll
        for (int i = 0; i < 4; i++) {
            const int idx = tid + i * 256;       // 0..1023 covers 128x32/4
            const int row = idx >> 3;
            const int c   = (idx & 7) * 4;
            *(float4*)&sA[row][c] = *(const float4*)&A[(size_t)(bm + row) * 256 + k0 + c];
            *(float4*)&sB[row][c] = *(const float4*)&B[(size_t)(bn + row) * 256 + k0 + c];
        }
        __syncthreads();

#pragma unroll
        for (int s = 0; s < 4; s++) {            // 4 x k8
            float a[2][4];
#pragma unroll
            for (int mf = 0; mf < 2; mf++) {
                const int rb = wm * 32 + mf * 16;
                a[mf][0] = sA[rb + g    ][s*8 + tq];
                a[mf][1] = sA[rb + g + 8][s*8 + tq];
                a[mf][2] = sA[rb + g    ][s*8 + tq + 4];
                a[mf][3] = sA[rb + g + 8][s*8 + tq + 4];
            }
#pragma unroll
            for (int nf = 0; nf < 8; nf++) {
                const int nb = wn * 64 + nf * 8 + g;
                const float b0 = sB[nb][s*8 + tq];
                const float b1 = sB[nb][s*8 + tq + 4];
#pragma unroll
                for (int mf = 0; mf < 2; mf++)
                    mma_tf32(acc[mf][nf], a[mf], b0, b1);
            }
        }
    }

#pragma unroll
    for (int mf = 0; mf < 2; mf++) {
        const int r0 = bm + wm * 32 + mf * 16 + g;
#pragma unroll
        for (int nf = 0; nf < 8; nf++) {
            const int c0 = bn + wn * 64 + nf * 8 + t2;
            epi(r0,     c0,     acc[mf][nf][0]);
            epi(r0,     c0 + 1, acc[mf][nf][1]);
            epi(r0 + 8, c0,     acc[mf][nf][2]);
            epi(r0 + 8, c0 + 1, acc[mf][nf][3]);
        }
    }
}

__global__ __launch_bounds__(256) void qkv_mma_kernel()
{
    QkvEpi epi;
    mma_gemm(g_xr, g_wqr, blockIdx.x * 128, blockIdx.y * 128, epi);
}

__global__ __launch_bounds__(256) void proj_mma_kernel(
    float* __restrict__ out, const float* __restrict__ bias)
{
    ProjEpi epi{out, bias};
    mma_gemm(g_att, g_wpr, blockIdx.x * 128, blockIdx.y * 128, epi);
}

// ---------------------------------------------------------------------------
// TF32 tensor-core flash attention. Block = 4 warps x 16 q-rows = 64 rows.
// S single-pass tf32; PV via quad-shuffle remap of P into A-fragment layout.
// ---------------------------------------------------------------------------
#define KST 36   // sK row stride (floats)
#define VST 68   // sV row stride (floats)

__global__ __launch_bounds__(128) void attn_kernel(const void* __restrict__ kpm)
{
    __shared__ __align__(16) float sK[64][KST];   // [key][dh]
    __shared__ __align__(16) float sV[32][VST];   // [dh][key]

    const int bh = blockIdx.y;
    const int b  = bh >> 3;
    const int h  = bh & 7;
    const int tid  = threadIdx.x;
    const int warp = tid >> 5;
    const int lane = tid & 31;
    const int g  = lane >> 2;
    const int tq = lane & 3;
    const int t2 = tq * 2;
    const int r0 = blockIdx.x * 64 + warp * 16;

    const int len = read_len(kpm, b);
    const float scale = 0.17677669529663687f;   // 1/sqrt(32)

    // Q fragments: 4 k8 steps x 4 regs (values already tf32-rounded)
    float q[4][4];
    {
        const float* qb = g_q + ((size_t)bh * SEQ + r0) * DH;
#pragma unroll
        for (int s = 0; s < 4; s++) {
            q[s][0] = qb[(size_t)g * DH       + s*8 + tq];
            q[s][1] = qb[(size_t)(g+8) * DH   + s*8 + tq];
            q[s][2] = qb[(size_t)g * DH       + s*8 + tq + 4];
            q[s][3] = qb[(size_t)(g+8) * DH   + s*8 + tq + 4];
        }
    }

    float O[4][4];
#pragma unroll
    for (int i = 0; i < 4; i++)
#pragma unroll
        for (int j = 0; j < 4; j++) O[i][j] = 0.f;
    float m0 = -CUDART_INF_F, m1 = -CUDART_INF_F;
    float l0 = 0.f, l1 = 0.f;

    const int ntiles = (len + 63) >> 6;
    for (int kt = 0; kt < ntiles; kt++) {
        const int k0 = kt * 64;
        __syncthreads();
        {
            const float* gk = g_k + ((size_t)bh * SEQ + k0) * DH;
            const float* gv = g_v + (size_t)bh * DH * SEQ + k0;
#pragma unroll
            for (int it = 0; it < 4; it++) {
                const int idx = tid + it * 128;       // 0..511
                const int krr = idx >> 3, kc = (idx & 7) * 4;
                *(float4*)&sK[krr][kc] = *(const float4*)(gk + (size_t)krr * DH + kc);
                const int vrr = idx >> 4, vc = (idx & 15) * 4;
                *(float4*)&sV[vrr][vc] = *(const float4*)(gv + (size_t)vrr * SEQ + vc);
            }
        }
        __syncthreads();

        // ---- S = Q K^T (16 x 64), single-pass tf32 ----
        float S[8][4];
#pragma unroll
        for (int nt = 0; nt < 8; nt++) {
            float* s = S[nt];
            s[0] = s[1] = s[2] = s[3] = 0.f;
            const int key = nt * 8 + g;
#pragma unroll
            for (int ss = 0; ss < 4; ss++) {
                const float b0 = sK[key][ss*8 + tq];
                const float b1 = sK[key][ss*8 + tq + 4];
                mma_tf32(s, q[ss], b0, b1);
            }
        }

        // ---- scale + mask ----
#pragma unroll
        for (int nt = 0; nt < 8; nt++) {
            const int kcol = k0 + nt * 8 + t2;
            const bool v0 = kcol < len, v1 = (kcol + 1) < len;
            S[nt][0] = v0 ? S[nt][0] * scale : -CUDART_INF_F;
            S[nt][1] = v1 ? S[nt][1] * scale : -CUDART_INF_F;
            S[nt][2] = v0 ? S[nt][2] * scale : -CUDART_INF_F;
            S[nt][3] = v1 ? S[nt][3] * scale : -CUDART_INF_F;
        }

        // ---- online softmax (rows g and g+8) ----
        float rm0 = -CUDART_INF_F, rm1 = -CUDART_INF_F;
#pragma unroll
        for (int nt = 0; nt < 8; nt++) {
            rm0 = fmaxf(rm0, fmaxf(S[nt][0], S[nt][1]));
            rm1 = fmaxf(rm1, fmaxf(S[nt][2], S[nt][3]));
        }
        rm0 = fmaxf(rm0, __shfl_xor_sync(0xffffffffu, rm0, 1));
        rm0 = fmaxf(rm0, __shfl_xor_sync(0xffffffffu, rm0, 2));
        rm1 = fmaxf(rm1, __shfl_xor_sync(0xffffffffu, rm1, 1));
        rm1 = fmaxf(rm1, __shfl_xor_sync(0xffffffffu, rm1, 2));

        const float nm0 = fmaxf(m0, rm0), nm1 = fmaxf(m1, rm1);
        const float cr0 = __expf(m0 - nm0), cr1 = __expf(m1 - nm1);
        m0 = nm0; m1 = nm1;
        l0 *= cr0; l1 *= cr1;
#pragma unroll
        for (int dn = 0; dn < 4; dn++) {
            O[dn][0] *= cr0; O[dn][1] *= cr0;
            O[dn][2] *= cr1; O[dn][3] *= cr1;
        }

        float ps0 = 0.f, ps1 = 0.f;
#pragma unroll
        for (int nt = 0; nt < 8; nt++) {
            S[nt][0] = __expf(S[nt][0] - m0);
            S[nt][1] = __expf(S[nt][1] - m0);
            S[nt][2] = __expf(S[nt][2] - m1);
            S[nt][3] = __expf(S[nt][3] - m1);
            ps0 += S[nt][0] + S[nt][1];
            ps1 += S[nt][2] + S[nt][3];
        }
        ps0 += __shfl_xor_sync(0xffffffffu, ps0, 1);
        ps0 += __shfl_xor_sync(0xffffffffu, ps0, 2);
        ps1 += __shfl_xor_sync(0xffffffffu, ps1, 1);
        ps1 += __shfl_xor_sync(0xffffffffu, ps1, 2);
        l0 += ps0; l1 += ps1;

        // ---- O += P V : remap P (acc layout cols 2tq,2tq+1) to A-frag layout
        //      (cols tq, tq+4) via intra-quad shuffles, then tf32 mma ----
        const int q0l = (lane & ~3) | (tq >> 1);        // src lane for col tq
        const int q1l = q0l + 2;                        // src lane for col tq+4
        const bool odd = tq & 1;
#pragma unroll
        for (int ss = 0; ss < 8; ss++) {
            const float v00 = __shfl_sync(0xffffffffu, S[ss][0], q0l);
            const float v01 = __shfl_sync(0xffffffffu, S[ss][1], q0l);
            const float v10 = __shfl_sync(0xffffffffu, S[ss][2], q0l);
            const float v11 = __shfl_sync(0xffffffffu, S[ss][3], q0l);
            const float w00 = __shfl_sync(0xffffffffu, S[ss][0], q1l);
            const float w01 = __shfl_sync(0xffffffffu, S[ss][1], q1l);
            const float w10 = __shfl_sync(0xffffffffu, S[ss][2], q1l);
            const float w11 = __shfl_sync(0xffffffffu, S[ss][3], q1l);
            float a[4];
            a[0] = tf32f(odd ? v01 : v00);   // P[g][8ss+tq]
            a[1] = tf32f(odd ? v11 : v10);   // P[g+8][8ss+tq]
            a[2] = tf32f(odd ? w01 : w00);   // P[g][8ss+tq+4]
            a[3] = tf32f(odd ? w11 : w10);   // P[g+8][8ss+tq+4]
#pragma unroll
            for (int dn = 0; dn < 4; dn++) {
                const float b0 = sV[dn*8 + g][ss*8 + tq];
                const float b1 = sV[dn*8 + g][ss*8 + tq + 4];
                mma_tf32(O[dn], a, b0, b1);
            }
        }
    }

    // ---- normalize + store (tf32-rounded for the proj GEMM) ----
    const float inv0 = 1.f / l0, inv1 = 1.f / l1;
    const int row0 = r0 + g, row1 = r0 + g + 8;
#pragma unroll
    for (int dn = 0; dn < 4; dn++) {
        const int col = h * 32 + dn * 8 + t2;
        const size_t i0 = ((size_t)(b * SEQ + row0)) * CH + col;
        const size_t i1 = ((size_t)(b * SEQ + row1)) * CH + col;
        g_att[i0]     = tf32f(O[dn][0] * inv0);
        g_att[i0 + 1] = tf32f(O[dn][1] * inv0);
        g_att[i1]     = tf32f(O[dn][2] * inv1);
        g_att[i1 + 1] = tf32f(O[dn][3] * inv1);
    }
}

// ---------------------------------------------------------------------------
// Launch
// ---------------------------------------------------------------------------
extern "C" void kernel_launch(void* const* d_in, const int* in_sizes, int n_in,
                              void* d_out, int out_size)
{
    (void)out_size;
    const float* x = nullptr; const void* kpm = nullptr;
    const float* w_qkv = nullptr; const float* w_proj = nullptr;
    const float* b_proj = nullptr;

    for (int i = 0; i < n_in; i++) {
        switch (in_sizes[i]) {
            case 2097152: x      = (const float*)d_in[i]; break;
            case 4:       kpm    = d_in[i];               break;
            case 196608:  w_qkv  = (const float*)d_in[i]; break;
            case 65536:   w_proj = (const float*)d_in[i]; break;
            case 256:     b_proj = (const float*)d_in[i]; break;
            default: break;
        }
    }
    float* out = (float*)d_out;

    float *xr, *wqr, *wpr;
    cudaGetSymbolAddress((void**)&xr,  g_xr);
    cudaGetSymbolAddress((void**)&wqr, g_wqr);
    cudaGetSymbolAddress((void**)&wpr, g_wpr);

    round_kernel<<<(2097152/4 + 255)/256, 256>>>(x, xr, 2097152/4);
    round_kernel<<<(196608/4  + 255)/256, 256>>>(w_qkv, wqr, 196608/4);
    round_kernel<<<(65536/4   + 255)/256, 256>>>(w_proj, wpr, 65536/4);

    {   // QKV mma: 8192 x 768
        dim3 grid(M_ROWS / 128, 768 / 128);
        qkv_mma_kernel<<<grid, 256>>>();
    }
    {   // attention: 64 q-rows per block
        dim3 grid(SEQ / 64, BH);
        attn_kernel<<<grid, 128>>>(kpm);
    }
    {   // proj mma: 8192 x 256
        dim3 grid(M_ROWS / 128, 256 / 128);
        proj_mma_kernel<<<grid, 256>>>(out, b_proj);
    }
}